// round 9
// baseline (speedup 1.0000x reference)
#include <cuda_runtime.h>
#include <cuda_fp16.h>
#include <cstdint>
#include <cstddef>

#define TT 16
#define HEADS 8
#define DH 40
#define CC 320
#define SPATIAL 1024
#define NSLAB 64
#define SLAB (CC * SPATIAL)
#define NELEM (1ull * NSLAB * SLAB)   // 20,971,520

// fp16 scratch: Q,K,V,O (4 x NELEM) + 4 converted W matrices
__device__ __half g_hbuf[4ull * NELEM + 4ull * CC * CC];

// ================= helpers =================
__device__ __forceinline__ uint32_t smem_u32(const void* p) {
    uint32_t a;
    asm("{ .reg .u64 t; cvta.to.shared.u64 t, %1; cvt.u32.u64 %0, t; }"
        : "=r"(a) : "l"(p));
    return a;
}
__device__ __forceinline__ void ldsm4(uint32_t* r, uint32_t a) {
    asm volatile("ldmatrix.sync.aligned.m8n8.x4.shared.b16 {%0,%1,%2,%3}, [%4];"
                 : "=r"(r[0]), "=r"(r[1]), "=r"(r[2]), "=r"(r[3]) : "r"(a));
}
__device__ __forceinline__ void ldsm4t(uint32_t* r, uint32_t a) {
    asm volatile("ldmatrix.sync.aligned.m8n8.x4.trans.shared.b16 {%0,%1,%2,%3}, [%4];"
                 : "=r"(r[0]), "=r"(r[1]), "=r"(r[2]), "=r"(r[3]) : "r"(a));
}
__device__ __forceinline__ void mma16(float* c, const uint32_t* a,
                                      uint32_t b0, uint32_t b1) {
    asm volatile(
        "mma.sync.aligned.m16n8k16.row.col.f32.f16.f16.f32 "
        "{%0,%1,%2,%3},{%4,%5,%6,%7},{%8,%9},{%0,%1,%2,%3};"
        : "+f"(c[0]), "+f"(c[1]), "+f"(c[2]), "+f"(c[3])
        : "r"(a[0]), "r"(a[1]), "r"(a[2]), "r"(a[3]), "r"(b0), "r"(b1));
}
#define CP_ASYNC(dst, src, sz) \
    asm volatile("cp.async.cg.shared.global [%0], [%1], 16, %2;" \
                 :: "r"(dst), "l"(src), "r"(sz))
#define CP_COMMIT() asm volatile("cp.async.commit_group;" ::: "memory")

__device__ __forceinline__ __half2 u2h2(uint32_t u) {
    __half2 h; *(uint32_t*)&h = u; return h;
}

// ================= W conversion =================
__global__ void cvt_w(const float* __restrict__ Wq, const float* __restrict__ Wk,
                      const float* __restrict__ Wv, const float* __restrict__ Wo,
                      __half* __restrict__ dst) {
    const int z = blockIdx.y;
    const int i = blockIdx.x * 1024 + threadIdx.x;   // < 102400
    const float* s = (z == 0) ? Wq : (z == 1) ? Wk : (z == 2) ? Wv : Wo;
    dst[(size_t)z * CC * CC + i] = __float2half_rn(s[i]);
}

// ================= fp16 tensor-core GEMM =================
// C[m0:+128, n0:+128] = W[320,320] @ X[320,1024] (K=320, 10 tiles of BK=32)
// 8 warps (2m x 4n), warp tile 64x32, mma.m16n8k16, fp32 accum, 3-stage ring.
// BF32: B operand read as fp32 from gmem, converted during STS (kills cvt_x).
#define APITCH 40
#define BPITCH 136
#define STAGEB 18944

template <bool EPI, bool BF32>
__device__ __forceinline__ void tc_gemm(
    const __half* __restrict__ W, const void* __restrict__ Xv,
    void* __restrict__ Cout, const float* __restrict__ bias,
    const float* __restrict__ R, int m0, int n0)
{
    extern __shared__ char smem[];
    const int tid = threadIdx.x;
    const int lane = tid & 31, wid = tid >> 5;
    const int wm = (wid & 1) * 64, wn = (wid >> 1) * 32;
    const uint32_t sb = smem_u32(smem);

    float c[4][4][4];
#pragma unroll
    for (int a = 0; a < 4; a++)
#pragma unroll
        for (int b = 0; b < 4; b++)
#pragma unroll
            for (int d = 0; d < 4; d++) c[a][b][d] = 0.f;

    auto stage_a = [&](int i) {
        const int kt = i * 32;
        const uint32_t as = sb + (uint32_t)(i % 3) * STAGEB;
#pragma unroll
        for (int t = 0; t < 2; t++) {
            const int idx = t * 256 + tid;
            const int row = idx >> 2, ch = idx & 3;
            const __half* src = W + (size_t)(m0 + row) * CC + kt + ch * 8;
            const int sz = (m0 + row < CC) ? 16 : 0;
            CP_ASYNC(as + (uint32_t)(row * (APITCH * 2) + ch * 16), src, sz);
        }
        if (!BF32) {
            const __half* X = (const __half*)Xv;
            const uint32_t bs = as + 10240u;
#pragma unroll
            for (int t = 0; t < 2; t++) {
                const int idx = t * 256 + tid;
                const int k = idx >> 4, nc = idx & 15;
                const __half* src = X + (size_t)(kt + k) * SPATIAL + n0 + nc * 8;
                CP_ASYNC(bs + (uint32_t)(k * (BPITCH * 2) + nc * 16), src, 16);
            }
        }
        CP_COMMIT();
    };

    float4 breg[4];
    auto ldg_b = [&](int i) {
        if (BF32) {
            const float* X = (const float*)Xv;
            const int kt = i * 32;
#pragma unroll
            for (int t = 0; t < 4; t++) {
                const int idx = t * 256 + tid;
                const int k = idx >> 5, nc = idx & 31;
                breg[t] = *(const float4*)(X + (size_t)(kt + k) * SPATIAL +
                                           n0 + nc * 4);
            }
        }
    };
    auto sts_b = [&](int i) {
        if (BF32) {
            const uint32_t bs = sb + (uint32_t)(i % 3) * STAGEB + 10240u;
#pragma unroll
            for (int t = 0; t < 4; t++) {
                const int idx = t * 256 + tid;
                const int k = idx >> 5, nc = idx & 31;
                __half2 h0 = __floats2half2_rn(breg[t].x, breg[t].y);
                __half2 h1 = __floats2half2_rn(breg[t].z, breg[t].w);
                asm volatile("st.shared.v2.b32 [%0], {%1,%2};"
                             :: "r"(bs + (uint32_t)(k * (BPITCH * 2) + nc * 8)),
                                "r"(*(uint32_t*)&h0), "r"(*(uint32_t*)&h1)
                             : "memory");
            }
        }
    };

    if (BF32) {
        ldg_b(0);
        stage_a(0);
        stage_a(1);
        sts_b(0);
        ldg_b(1);
    } else {
        stage_a(0);
        stage_a(1);
    }

    for (int i = 0; i < 10; i++) {
        if (i < 8) asm volatile("cp.async.wait_group 1;" ::: "memory");
        else       asm volatile("cp.async.wait_group 0;" ::: "memory");
        __syncthreads();

        const uint32_t as = sb + (uint32_t)(i % 3) * STAGEB;
        const uint32_t bs = as + 10240u;

#pragma unroll
        for (int ks = 0; ks < 2; ks++) {
            uint32_t af[4][4], bf[2][4];
#pragma unroll
            for (int mt = 0; mt < 4; mt++) {
                const uint32_t addr = as +
                    (uint32_t)((wm + mt * 16 + (lane & 15)) * (APITCH * 2) +
                               (lane >> 4) * 16 + ks * 32);
                ldsm4(af[mt], addr);
            }
#pragma unroll
            for (int nb = 0; nb < 2; nb++) {
                const uint32_t addr = bs +
                    (uint32_t)((ks * 16 + (lane & 15)) * (BPITCH * 2) +
                               (wn + nb * 16 + (lane >> 4) * 8) * 2);
                ldsm4t(bf[nb], addr);
            }
#pragma unroll
            for (int nt = 0; nt < 4; nt++) {
                const uint32_t b0 = bf[nt >> 1][(nt & 1) * 2];
                const uint32_t b1 = bf[nt >> 1][(nt & 1) * 2 + 1];
#pragma unroll
                for (int mt = 0; mt < 4; mt++)
                    mma16(c[mt][nt], af[mt], b0, b1);
            }
        }

        if (!BF32) __syncthreads();
        if (i + 2 < 10) stage_a(i + 2);
        if (BF32) {
            if (i + 1 < 10) sts_b(i + 1);   // buffer (i+1)%3: disjoint from compute(i)
            if (i + 2 < 10) ldg_b(i + 2);
        }
    }

    // ---- epilogue ----
#pragma unroll
    for (int mt = 0; mt < 4; mt++) {
#pragma unroll
        for (int nt = 0; nt < 4; nt++) {
            const int r0 = m0 + wm + mt * 16 + (lane >> 2);
            const int col = n0 + wn + nt * 8 + (lane & 3) * 2;
            if (EPI) {
                float* C = (float*)Cout;
                if (r0 < CC) {
                    const size_t o0 = (size_t)r0 * SPATIAL + col;
                    const float bb = bias[r0];
                    const float2 x0 = *(const float2*)(R + o0);
                    *(float2*)(C + o0) = make_float2(c[mt][nt][0] + bb + x0.x,
                                                     c[mt][nt][1] + bb + x0.y);
                }
                if (r0 + 8 < CC) {
                    const size_t o1 = (size_t)(r0 + 8) * SPATIAL + col;
                    const float bb = bias[r0 + 8];
                    const float2 x1 = *(const float2*)(R + o1);
                    *(float2*)(C + o1) = make_float2(c[mt][nt][2] + bb + x1.x,
                                                     c[mt][nt][3] + bb + x1.y);
                }
            } else {
                __half* C = (__half*)Cout;
                if (r0 < CC) {
                    *(__half2*)(C + (size_t)r0 * SPATIAL + col) =
                        __floats2half2_rn(c[mt][nt][0], c[mt][nt][1]);
                }
                if (r0 + 8 < CC) {
                    *(__half2*)(C + (size_t)(r0 + 8) * SPATIAL + col) =
                        __floats2half2_rn(c[mt][nt][2], c[mt][nt][3]);
                }
            }
        }
    }
}

__global__ __launch_bounds__(256, 2) void qkv_tc(
    const __half* __restrict__ Wh, const float* __restrict__ X,
    __half* __restrict__ out)
{
    const int slab = blockIdx.z;
    const int wsel = blockIdx.y / 3, mt = blockIdx.y % 3;
    tc_gemm<false, true>(Wh + (size_t)wsel * CC * CC,
                         X + (size_t)slab * SLAB,
                         out + (size_t)wsel * NELEM + (size_t)slab * SLAB,
                         nullptr, nullptr, mt * 128, blockIdx.x * 128);
}

__global__ __launch_bounds__(256, 2) void o_tc(
    const __half* __restrict__ Wh, const __half* __restrict__ O,
    const float* __restrict__ bo, const float* __restrict__ X,
    float* __restrict__ out)
{
    const int slab = blockIdx.z;
    tc_gemm<true, false>(Wh + 3ull * CC * CC, O + (size_t)slab * SLAB,
                         out + (size_t)slab * SLAB, bo,
                         X + (size_t)slab * SLAB,
                         blockIdx.y * 128, blockIdx.x * 128);
}

// ================= Attention (r7 warp-uniform + LDS.64 packing) ================
// Block = (b, h, 32 spatial). 256 thr = 8 warps; warp tg does t=tg, t=15-tg.
// K,V smem as uint2 [f][j2=dpair/2][32 lanes] (8B loads, conflict-free);
// rel tables packed halves [diff][40]. 87.2KB smem -> 2 CTA/SM.
#define J2 (DH / 4)   // 10 quad-groups

__global__ __launch_bounds__(256, 2) void attn_kernel(
    const __half* __restrict__ Qg, const __half* __restrict__ Kg,
    const __half* __restrict__ Vg, __half* __restrict__ Og,
    const float* __restrict__ relk, const float* __restrict__ relv)
{
    extern __shared__ char smc[];
    uint2* Kp = (uint2*)smc;                    // 16*10*32 = 5120 uint2 (40960B)
    uint2* Vp = Kp + TT * J2 * 32;              // 40960B
    uint2* Rkp = Vp + TT * J2 * 32;             // 33*10 uint2 (2640B)
    uint2* Rvp = Rkp + 33 * J2;                 // 2640B  (total 87200B)

    const int b = blockIdx.z;
    const int h = blockIdx.y;
    const int s0 = blockIdx.x * 32;
    const int tid = threadIdx.x;

    // stage K,V: coalesced gmem half reads, scatter into quad layout
    __half* Ksh = (__half*)Kp;
    __half* Vsh = (__half*)Vp;
    for (int i = tid; i < TT * DH * 32; i += 256) {
        const int row = i >> 5, sl2 = i & 31;
        const int f = row / DH, dd = row - f * DH;
        const size_t g =
            ((size_t)((b * TT + f) * CC + h * DH + dd)) * SPATIAL + s0 + sl2;
        const int w = ((f * J2 + (dd >> 2)) * 32 + sl2) * 4 + (dd & 3);
        Ksh[w] = Kg[g];
        Vsh[w] = Vg[g];
    }
    // rel tables: linear [diff][dd] halves (10 uint2 per diff)
    __half* Rkh = (__half*)Rkp;
    __half* Rvh = (__half*)Rvp;
    for (int i = tid; i < 33 * DH; i += 256) {
        Rkh[i] = __float2half_rn(relk[i]);
        Rvh[i] = __float2half_rn(relv[i]);
    }
    __syncthreads();

    const int sl = tid & 31;
    const int tg = tid >> 5;
    const float scale = 0.15811388300841898f;  // 40^-0.5

    for (int rep = 0; rep < 2; rep++) {
        const int t = rep ? (15 - tg) : tg;    // warp-uniform
        const size_t base =
            ((size_t)((b * TT + t) * CC + h * DH)) * SPATIAL + s0 + sl;

        float qo[DH];   // q (pre-scaled) during sim phase, o during AV phase
#pragma unroll
        for (int dd = 0; dd < DH; dd++)
            qo[dd] = __half2float(Qg[base + (size_t)dd * SPATIAL]) * scale;

        float sim[TT];
        float mx = -1e30f;
#pragma unroll
        for (int sp = 0; sp < TT; sp++) {
            if (sp > t) break;                 // warp-uniform
            const uint2* kp = Kp + (sp * J2) * 32 + sl;
            const uint2* rp = Rkp + (sp - t + TT) * J2;
            float p0 = 0.f, p1 = 0.f, p2 = 0.f, p3 = 0.f;
#pragma unroll
            for (int j = 0; j < J2; j++) {
                const uint2 kv = kp[j * 32];
                const uint2 rv = rp[j];
                const float2 f0 = __half22float2(__hadd2(u2h2(kv.x), u2h2(rv.x)));
                const float2 f1 = __half22float2(__hadd2(u2h2(kv.y), u2h2(rv.y)));
                p0 = fmaf(qo[4 * j],     f0.x, p0);
                p1 = fmaf(qo[4 * j + 1], f0.y, p1);
                p2 = fmaf(qo[4 * j + 2], f1.x, p2);
                p3 = fmaf(qo[4 * j + 3], f1.y, p3);
            }
            const float acc = (p0 + p1) + (p2 + p3);
            sim[sp] = acc;
            mx = fmaxf(mx, acc);
        }
        float den = 0.f;
#pragma unroll
        for (int sp = 0; sp < TT; sp++) {
            if (sp > t) break;
            const float e = __expf(sim[sp] - mx);
            sim[sp] = e;
            den += e;
        }
        const float inv = 1.f / den;

#pragma unroll
        for (int dd = 0; dd < DH; dd++) qo[dd] = 0.f;   // q dead; reuse as o
#pragma unroll
        for (int sp = 0; sp < TT; sp++) {
            if (sp > t) break;
            const float a = sim[sp];
            const uint2* vp = Vp + (sp * J2) * 32 + sl;
            const uint2* rp = Rvp + (sp - t + TT) * J2;
#pragma unroll
            for (int j = 0; j < J2; j++) {
                const uint2 vv = vp[j * 32];
                const uint2 rv = rp[j];
                const float2 f0 = __half22float2(__hadd2(u2h2(vv.x), u2h2(rv.x)));
                const float2 f1 = __half22float2(__hadd2(u2h2(vv.y), u2h2(rv.y)));
                qo[4 * j]     = fmaf(a, f0.x, qo[4 * j]);
                qo[4 * j + 1] = fmaf(a, f0.y, qo[4 * j + 1]);
                qo[4 * j + 2] = fmaf(a, f1.x, qo[4 * j + 2]);
                qo[4 * j + 3] = fmaf(a, f1.y, qo[4 * j + 3]);
            }
        }
#pragma unroll
        for (int dd = 0; dd < DH; dd++)
            Og[base + (size_t)dd * SPATIAL] = __float2half_rn(qo[dd] * inv);
    }
}

// ================= launch =================
extern "C" void kernel_launch(void* const* d_in, const int* in_sizes, int n_in,
                              void* d_out, int out_size) {
    const float* x  = (const float*)d_in[0];
    const float* Wq = (const float*)d_in[1];
    const float* Wk = (const float*)d_in[2];
    const float* Wv = (const float*)d_in[3];
    const float* Wo = (const float*)d_in[4];
    const float* bo = (const float*)d_in[5];
    const float* rk = (const float*)d_in[6];
    const float* rv = (const float*)d_in[7];
    float* out = (float*)d_out;

    __half* hb = nullptr;
    cudaGetSymbolAddress((void**)&hb, g_hbuf);
    __half* Q  = hb;
    __half* K  = hb + 1ull * NELEM;
    __half* V  = hb + 2ull * NELEM;
    __half* O  = hb + 3ull * NELEM;
    __half* Wh = hb + 4ull * NELEM;

    cvt_w<<<dim3(100, 4), 1024>>>(Wq, Wk, Wv, Wo, Wh);

    const int gsm = 3 * STAGEB;  // 56832
    cudaFuncSetAttribute((const void*)qkv_tc,
                         cudaFuncAttributeMaxDynamicSharedMemorySize, gsm);
    cudaFuncSetAttribute((const void*)o_tc,
                         cudaFuncAttributeMaxDynamicSharedMemorySize, gsm);

    qkv_tc<<<dim3(SPATIAL / 128, 9, NSLAB), 256, gsm>>>(Wh, x, hb);

    const int asmb = 87200;
    cudaFuncSetAttribute((const void*)attn_kernel,
                         cudaFuncAttributeMaxDynamicSharedMemorySize, asmb);
    attn_kernel<<<dim3(SPATIAL / 32, HEADS, 4), 256, asmb>>>(Q, K, V, O, rk, rv);

    o_tc<<<dim3(SPATIAL / 128, 3, NSLAB), 256, gsm>>>(Wh, O, bo, x, out);
}

// round 10
// speedup vs baseline: 1.1014x; 1.1014x over previous
#include <cuda_runtime.h>
#include <cuda_fp16.h>
#include <cstdint>
#include <cstddef>

#define TT 16
#define HEADS 8
#define DH 40
#define CC 320
#define SPATIAL 1024
#define NSLAB 64
#define SLAB (CC * SPATIAL)
#define NELEM (1ull * NSLAB * SLAB)   // 20,971,520

// fp16 scratch: Q,K,V,O, Xh (5 x NELEM) + 4 converted W matrices
__device__ __half g_hbuf[5ull * NELEM + 4ull * CC * CC];

// ================= helpers =================
__device__ __forceinline__ uint32_t smem_u32(const void* p) {
    uint32_t a;
    asm("{ .reg .u64 t; cvta.to.shared.u64 t, %1; cvt.u32.u64 %0, t; }"
        : "=r"(a) : "l"(p));
    return a;
}
__device__ __forceinline__ void ldsm4(uint32_t* r, uint32_t a) {
    asm volatile("ldmatrix.sync.aligned.m8n8.x4.shared.b16 {%0,%1,%2,%3}, [%4];"
                 : "=r"(r[0]), "=r"(r[1]), "=r"(r[2]), "=r"(r[3]) : "r"(a));
}
__device__ __forceinline__ void ldsm4t(uint32_t* r, uint32_t a) {
    asm volatile("ldmatrix.sync.aligned.m8n8.x4.trans.shared.b16 {%0,%1,%2,%3}, [%4];"
                 : "=r"(r[0]), "=r"(r[1]), "=r"(r[2]), "=r"(r[3]) : "r"(a));
}
__device__ __forceinline__ void mma16(float* c, const uint32_t* a,
                                      uint32_t b0, uint32_t b1) {
    asm volatile(
        "mma.sync.aligned.m16n8k16.row.col.f32.f16.f16.f32 "
        "{%0,%1,%2,%3},{%4,%5,%6,%7},{%8,%9},{%0,%1,%2,%3};"
        : "+f"(c[0]), "+f"(c[1]), "+f"(c[2]), "+f"(c[3])
        : "r"(a[0]), "r"(a[1]), "r"(a[2]), "r"(a[3]), "r"(b0), "r"(b1));
}
#define CP_ASYNC(dst, src, sz) \
    asm volatile("cp.async.cg.shared.global [%0], [%1], 16, %2;" \
                 :: "r"(dst), "l"(src), "r"(sz))
#define CP_COMMIT() asm volatile("cp.async.commit_group;" ::: "memory")

__device__ __forceinline__ __half2 u2h2(uint32_t u) {
    __half2 h; *(uint32_t*)&h = u; return h;
}

// ================= conversion kernels =================
__global__ __launch_bounds__(256) void cvt_x(const float* __restrict__ x,
                                             __half* __restrict__ xh) {
    const size_t i = ((size_t)blockIdx.x * 256 + threadIdx.x) * 8;
    float4 a = *(const float4*)(x + i);
    float4 b = *(const float4*)(x + i + 4);
    __half2 h[4] = { __floats2half2_rn(a.x, a.y), __floats2half2_rn(a.z, a.w),
                     __floats2half2_rn(b.x, b.y), __floats2half2_rn(b.z, b.w) };
    *(uint4*)(xh + i) = *(uint4*)h;
}
__global__ void cvt_w(const float* __restrict__ Wq, const float* __restrict__ Wk,
                      const float* __restrict__ Wv, const float* __restrict__ Wo,
                      __half* __restrict__ dst) {
    const int z = blockIdx.y;
    const int i = blockIdx.x * 1024 + threadIdx.x;   // < 102400
    const float* s = (z == 0) ? Wq : (z == 1) ? Wk : (z == 2) ? Wv : Wo;
    dst[(size_t)z * CC * CC + i] = __float2half_rn(s[i]);
}

// ================= fp16 tensor-core GEMM (round-6 structure, known good) ======
#define APITCH 40
#define BPITCH 136
#define STAGEB 18944

template <bool EPI>
__device__ __forceinline__ void tc_gemm(
    const __half* __restrict__ W, const __half* __restrict__ X,
    void* __restrict__ Cout, const float* __restrict__ bias,
    const float* __restrict__ R, int m0, int n0)
{
    extern __shared__ char smem[];
    const int tid = threadIdx.x;
    const int lane = tid & 31, wid = tid >> 5;
    const int wm = (wid & 1) * 64, wn = (wid >> 1) * 32;
    const uint32_t sb = smem_u32(smem);

    float c[4][4][4];
#pragma unroll
    for (int a = 0; a < 4; a++)
#pragma unroll
        for (int b = 0; b < 4; b++)
#pragma unroll
            for (int d = 0; d < 4; d++) c[a][b][d] = 0.f;

    auto stage = [&](int i) {
        const int kt = i * 32;
        const uint32_t as = sb + (uint32_t)(i % 3) * STAGEB;
        const uint32_t bs = as + 10240u;
#pragma unroll
        for (int t = 0; t < 2; t++) {
            const int idx = t * 256 + tid;
            const int row = idx >> 2, ch = idx & 3;
            const __half* src = W + (size_t)(m0 + row) * CC + kt + ch * 8;
            const int sz = (m0 + row < CC) ? 16 : 0;
            CP_ASYNC(as + (uint32_t)(row * (APITCH * 2) + ch * 16), src, sz);
        }
#pragma unroll
        for (int t = 0; t < 2; t++) {
            const int idx = t * 256 + tid;
            const int k = idx >> 4, nc = idx & 15;
            const __half* src = X + (size_t)(kt + k) * SPATIAL + n0 + nc * 8;
            CP_ASYNC(bs + (uint32_t)(k * (BPITCH * 2) + nc * 16), src, 16);
        }
        CP_COMMIT();
    };

    stage(0);
    stage(1);

    for (int i = 0; i < 10; i++) {
        if (i < 8) asm volatile("cp.async.wait_group 1;" ::: "memory");
        else       asm volatile("cp.async.wait_group 0;" ::: "memory");
        __syncthreads();
        if (i + 2 < 10) stage(i + 2);

        const uint32_t as = sb + (uint32_t)(i % 3) * STAGEB;
        const uint32_t bs = as + 10240u;

#pragma unroll
        for (int ks = 0; ks < 2; ks++) {
            uint32_t af[4][4], bf[2][4];
#pragma unroll
            for (int mt = 0; mt < 4; mt++) {
                const uint32_t addr = as +
                    (uint32_t)((wm + mt * 16 + (lane & 15)) * (APITCH * 2) +
                               (lane >> 4) * 16 + ks * 32);
                ldsm4(af[mt], addr);
            }
#pragma unroll
            for (int nb = 0; nb < 2; nb++) {
                const uint32_t addr = bs +
                    (uint32_t)((ks * 16 + (lane & 15)) * (BPITCH * 2) +
                               (wn + nb * 16 + (lane >> 4) * 8) * 2);
                ldsm4t(bf[nb], addr);
            }
#pragma unroll
            for (int nt = 0; nt < 4; nt++) {
                const uint32_t b0 = bf[nt >> 1][(nt & 1) * 2];
                const uint32_t b1 = bf[nt >> 1][(nt & 1) * 2 + 1];
#pragma unroll
                for (int mt = 0; mt < 4; mt++)
                    mma16(c[mt][nt], af[mt], b0, b1);
            }
        }
        __syncthreads();
    }

    // ---- epilogue ----
#pragma unroll
    for (int mt = 0; mt < 4; mt++) {
#pragma unroll
        for (int nt = 0; nt < 4; nt++) {
            const int r0 = m0 + wm + mt * 16 + (lane >> 2);
            const int col = n0 + wn + nt * 8 + (lane & 3) * 2;
            if (EPI) {
                float* C = (float*)Cout;
                if (r0 < CC) {
                    const size_t o0 = (size_t)r0 * SPATIAL + col;
                    const float bb = bias[r0];
                    const float2 x0 = *(const float2*)(R + o0);
                    *(float2*)(C + o0) = make_float2(c[mt][nt][0] + bb + x0.x,
                                                     c[mt][nt][1] + bb + x0.y);
                }
                if (r0 + 8 < CC) {
                    const size_t o1 = (size_t)(r0 + 8) * SPATIAL + col;
                    const float bb = bias[r0 + 8];
                    const float2 x1 = *(const float2*)(R + o1);
                    *(float2*)(C + o1) = make_float2(c[mt][nt][2] + bb + x1.x,
                                                     c[mt][nt][3] + bb + x1.y);
                }
            } else {
                __half* C = (__half*)Cout;
                if (r0 < CC) {
                    *(__half2*)(C + (size_t)r0 * SPATIAL + col) =
                        __floats2half2_rn(c[mt][nt][0], c[mt][nt][1]);
                }
                if (r0 + 8 < CC) {
                    *(__half2*)(C + (size_t)(r0 + 8) * SPATIAL + col) =
                        __floats2half2_rn(c[mt][nt][2], c[mt][nt][3]);
                }
            }
        }
    }
}

__global__ __launch_bounds__(256, 2) void qkv_tc(
    const __half* __restrict__ Wh, const __half* __restrict__ Xh,
    __half* __restrict__ out)
{
    const int slab = blockIdx.z;
    const int wsel = blockIdx.y / 3, mt = blockIdx.y % 3;
    tc_gemm<false>(Wh + (size_t)wsel * CC * CC, Xh + (size_t)slab * SLAB,
                   out + (size_t)wsel * NELEM + (size_t)slab * SLAB,
                   nullptr, nullptr, mt * 128, blockIdx.x * 128);
}

__global__ __launch_bounds__(256, 2) void o_tc(
    const __half* __restrict__ Wh, const __half* __restrict__ O,
    const float* __restrict__ bo, const float* __restrict__ X,
    float* __restrict__ out)
{
    const int slab = blockIdx.z;
    tc_gemm<true>(Wh + 3ull * CC * CC, O + (size_t)slab * SLAB,
                  out + (size_t)slab * SLAB, bo, X + (size_t)slab * SLAB,
                  blockIdx.y * 128, blockIdx.x * 128);
}

// ================= Attention =================
// Block = (b, h, 32 spatial). 256 thr = 8 warps; warp tg does t=tg, t=15-tg.
// K,V smem as uint2 [f][j2][32 lanes] (8B conflict-free compute loads);
// staging via uint4 gmem loads (16B/thread). 87.2KB smem -> 2 CTA/SM.
#define J2 (DH / 4)   // 10 quad-groups

__global__ __launch_bounds__(256, 2) void attn_kernel(
    const __half* __restrict__ Qg, const __half* __restrict__ Kg,
    const __half* __restrict__ Vg, __half* __restrict__ Og,
    const float* __restrict__ relk, const float* __restrict__ relv)
{
    extern __shared__ char smc[];
    uint2* Kp = (uint2*)smc;                    // 16*10*32 uint2 = 40960B
    uint2* Vp = Kp + TT * J2 * 32;              // 40960B
    uint2* Rkp = Vp + TT * J2 * 32;             // 33*10 uint2 = 2640B
    uint2* Rvp = Rkp + 33 * J2;                 // 2640B  (total 87200B)

    const int b = blockIdx.z;
    const int h = blockIdx.y;
    const int s0 = blockIdx.x * 32;
    const int tid = threadIdx.x;

    // ---- stage K,V: uint4 (8-half) gmem loads, STS.16 scatter into quad layout
    __half* Ksh = (__half*)Kp;
    __half* Vsh = (__half*)Vp;
    for (int i = tid; i < TT * DH * 4; i += 256) {   // 2560 uint4 per array
        const int row = i >> 2;                       // (f, dd)
        const int ch = (i & 3) * 8;                   // spatial chunk base
        const int f = row / DH, dd = row - f * DH;
        const size_t g =
            ((size_t)((b * TT + f) * CC + h * DH + dd)) * SPATIAL + s0 + ch;
        uint4 kk = *(const uint4*)(Kg + g);
        uint4 vv = *(const uint4*)(Vg + g);
        __half kh[8], vh[8];
        *(uint4*)kh = kk;
        *(uint4*)vh = vv;
        const int wb = (f * J2 + (dd >> 2)) * 32;
        const int e0 = dd & 3;
#pragma unroll
        for (int e = 0; e < 8; e++) {
            const int w = (wb + ch + e) * 4 + e0;
            Ksh[w] = kh[e];
            Vsh[w] = vh[e];
        }
    }
    // rel tables: linear [diff][dd] halves (10 uint2 per diff)
    __half* Rkh = (__half*)Rkp;
    __half* Rvh = (__half*)Rvp;
    for (int i = tid; i < 33 * DH; i += 256) {
        Rkh[i] = __float2half_rn(relk[i]);
        Rvh[i] = __float2half_rn(relv[i]);
    }
    __syncthreads();

    const int sl = tid & 31;
    const int tg = tid >> 5;
    const float scale = 0.15811388300841898f;  // 40^-0.5

    for (int rep = 0; rep < 2; rep++) {
        const int t = rep ? (15 - tg) : tg;    // warp-uniform
        const size_t base =
            ((size_t)((b * TT + t) * CC + h * DH)) * SPATIAL + s0 + sl;

        float qo[DH];   // q (pre-scaled) during sim phase, o during AV phase
#pragma unroll
        for (int dd = 0; dd < DH; dd++)
            qo[dd] = __half2float(Qg[base + (size_t)dd * SPATIAL]) * scale;

        float sim[TT];
        float mx = -1e30f;
#pragma unroll
        for (int sp = 0; sp < TT; sp++) {
            if (sp > t) break;                 // warp-uniform
            const uint2* kp = Kp + (sp * J2) * 32 + sl;
            const uint2* rp = Rkp + (sp - t + TT) * J2;
            float p0 = 0.f, p1 = 0.f, p2 = 0.f, p3 = 0.f;
#pragma unroll
            for (int j = 0; j < J2; j++) {
                const uint2 kv = kp[j * 32];
                const uint2 rv = rp[j];
                const float2 f0 = __half22float2(__hadd2(u2h2(kv.x), u2h2(rv.x)));
                const float2 f1 = __half22float2(__hadd2(u2h2(kv.y), u2h2(rv.y)));
                p0 = fmaf(qo[4 * j],     f0.x, p0);
                p1 = fmaf(qo[4 * j + 1], f0.y, p1);
                p2 = fmaf(qo[4 * j + 2], f1.x, p2);
                p3 = fmaf(qo[4 * j + 3], f1.y, p3);
            }
            const float acc = (p0 + p1) + (p2 + p3);
            sim[sp] = acc;
            mx = fmaxf(mx, acc);
        }
        float den = 0.f;
#pragma unroll
        for (int sp = 0; sp < TT; sp++) {
            if (sp > t) break;
            const float e = __expf(sim[sp] - mx);
            sim[sp] = e;
            den += e;
        }
        const float inv = 1.f / den;

#pragma unroll
        for (int dd = 0; dd < DH; dd++) qo[dd] = 0.f;   // q dead; reuse as o
#pragma unroll
        for (int sp = 0; sp < TT; sp++) {
            if (sp > t) break;
            const float a = sim[sp];
            const uint2* vp = Vp + (sp * J2) * 32 + sl;
            const uint2* rp = Rvp + (sp - t + TT) * J2;
#pragma unroll
            for (int j = 0; j < J2; j++) {
                const uint2 vv = vp[j * 32];
                const uint2 rv = rp[j];
                const float2 f0 = __half22float2(__hadd2(u2h2(vv.x), u2h2(rv.x)));
                const float2 f1 = __half22float2(__hadd2(u2h2(vv.y), u2h2(rv.y)));
                qo[4 * j]     = fmaf(a, f0.x, qo[4 * j]);
                qo[4 * j + 1] = fmaf(a, f0.y, qo[4 * j + 1]);
                qo[4 * j + 2] = fmaf(a, f1.x, qo[4 * j + 2]);
                qo[4 * j + 3] = fmaf(a, f1.y, qo[4 * j + 3]);
            }
        }
#pragma unroll
        for (int dd = 0; dd < DH; dd++)
            Og[base + (size_t)dd * SPATIAL] = __float2half_rn(qo[dd] * inv);
    }
}

// ================= launch =================
extern "C" void kernel_launch(void* const* d_in, const int* in_sizes, int n_in,
                              void* d_out, int out_size) {
    const float* x  = (const float*)d_in[0];
    const float* Wq = (const float*)d_in[1];
    const float* Wk = (const float*)d_in[2];
    const float* Wv = (const float*)d_in[3];
    const float* Wo = (const float*)d_in[4];
    const float* bo = (const float*)d_in[5];
    const float* rk = (const float*)d_in[6];
    const float* rv = (const float*)d_in[7];
    float* out = (float*)d_out;

    __half* hb = nullptr;
    cudaGetSymbolAddress((void**)&hb, g_hbuf);
    __half* Q  = hb;
    __half* K  = hb + 1ull * NELEM;
    __half* V  = hb + 2ull * NELEM;
    __half* O  = hb + 3ull * NELEM;
    __half* Xh = hb + 4ull * NELEM;
    __half* Wh = hb + 5ull * NELEM;

    cvt_w<<<dim3(100, 4), 1024>>>(Wq, Wk, Wv, Wo, Wh);
    cvt_x<<<(unsigned)(NELEM / (256 * 8)), 256>>>(x, Xh);

    const int gsm = 3 * STAGEB;  // 56832
    cudaFuncSetAttribute((const void*)qkv_tc,
                         cudaFuncAttributeMaxDynamicSharedMemorySize, gsm);
    cudaFuncSetAttribute((const void*)o_tc,
                         cudaFuncAttributeMaxDynamicSharedMemorySize, gsm);

    qkv_tc<<<dim3(SPATIAL / 128, 9, NSLAB), 256, gsm>>>(Wh, Xh, hb);

    const int asmb = 87200;
    cudaFuncSetAttribute((const void*)attn_kernel,
                         cudaFuncAttributeMaxDynamicSharedMemorySize, asmb);
    attn_kernel<<<dim3(SPATIAL / 32, HEADS, 4), 256, asmb>>>(Q, K, V, O, rk, rv);

    o_tc<<<dim3(SPATIAL / 128, 3, NSLAB), 256, gsm>>>(Wh, O, bo, x, out);
}

// round 11
// speedup vs baseline: 1.1349x; 1.0305x over previous
#include <cuda_runtime.h>
#include <cuda_fp16.h>
#include <cstdint>
#include <cstddef>

#define TT 16
#define HEADS 8
#define DH 40
#define CC 320
#define SPATIAL 1024
#define NSLAB 64
#define SLAB (CC * SPATIAL)
#define NELEM (1ull * NSLAB * SLAB)   // 20,971,520

// fp16 scratch: Q,K,V,O, Xh (5 x NELEM) + 4 converted W matrices
__device__ __half g_hbuf[5ull * NELEM + 4ull * CC * CC];

// ================= helpers =================
__device__ __forceinline__ uint32_t smem_u32(const void* p) {
    uint32_t a;
    asm("{ .reg .u64 t; cvta.to.shared.u64 t, %1; cvt.u32.u64 %0, t; }"
        : "=r"(a) : "l"(p));
    return a;
}
__device__ __forceinline__ void ldsm4(uint32_t* r, uint32_t a) {
    asm volatile("ldmatrix.sync.aligned.m8n8.x4.shared.b16 {%0,%1,%2,%3}, [%4];"
                 : "=r"(r[0]), "=r"(r[1]), "=r"(r[2]), "=r"(r[3]) : "r"(a));
}
__device__ __forceinline__ void ldsm4t(uint32_t* r, uint32_t a) {
    asm volatile("ldmatrix.sync.aligned.m8n8.x4.trans.shared.b16 {%0,%1,%2,%3}, [%4];"
                 : "=r"(r[0]), "=r"(r[1]), "=r"(r[2]), "=r"(r[3]) : "r"(a));
}
__device__ __forceinline__ void mma16(float* c, const uint32_t* a,
                                      uint32_t b0, uint32_t b1) {
    asm volatile(
        "mma.sync.aligned.m16n8k16.row.col.f32.f16.f16.f32 "
        "{%0,%1,%2,%3},{%4,%5,%6,%7},{%8,%9},{%0,%1,%2,%3};"
        : "+f"(c[0]), "+f"(c[1]), "+f"(c[2]), "+f"(c[3])
        : "r"(a[0]), "r"(a[1]), "r"(a[2]), "r"(a[3]), "r"(b0), "r"(b1));
}
#define CP_ASYNC(dst, src, sz) \
    asm volatile("cp.async.cg.shared.global [%0], [%1], 16, %2;" \
                 :: "r"(dst), "l"(src), "r"(sz))
#define CP_COMMIT() asm volatile("cp.async.commit_group;" ::: "memory")

__device__ __forceinline__ __half2 u2h2(uint32_t u) {
    __half2 h; *(uint32_t*)&h = u; return h;
}

// ================= fused conversion kernel =================
// blocks [0, XB): convert x -> Xh (8 floats/thread)
// blocks [XB, XB+WB): convert Wq|Wk|Wv|Wo -> Wh (8 floats/thread)
#define XB ((unsigned)(NELEM / 2048))        // 10240
#define WB ((unsigned)(4 * CC * CC / 2048))  // 200

__global__ __launch_bounds__(256) void cvt_all(
    const float* __restrict__ x,
    const float* __restrict__ Wq, const float* __restrict__ Wk,
    const float* __restrict__ Wv, const float* __restrict__ Wo,
    __half* __restrict__ xh, __half* __restrict__ wh)
{
    const unsigned bx = blockIdx.x;
    const float* src;
    __half* dst;
    size_t i;
    if (bx < XB) {
        i = ((size_t)bx * 256 + threadIdx.x) * 8;
        src = x; dst = xh;
    } else {
        i = ((size_t)(bx - XB) * 256 + threadIdx.x) * 8;   // < 409600
        const size_t wsz = (size_t)CC * CC;
        const int z = (int)(i / wsz);
        src = (z == 0) ? Wq : (z == 1) ? Wk : (z == 2) ? Wv : Wo;
        src -= z * wsz;   // index with global i
        dst = wh;
    }
    float4 a = *(const float4*)(src + i);
    float4 b = *(const float4*)(src + i + 4);
    __half2 h[4] = { __floats2half2_rn(a.x, a.y), __floats2half2_rn(a.z, a.w),
                     __floats2half2_rn(b.x, b.y), __floats2half2_rn(b.z, b.w) };
    *(uint4*)(dst + i) = *(uint4*)h;
}

// ================= fp16 tensor-core GEMM =================
// MB = rows per CTA (128 for qkv, 64 for o). BN=128, BK=32, K=320.
// 8 warps: (2m x 4n), warp tile (MB/2 x 32). 3-stage cp.async ring.
#define APITCH 40
#define BPITCH 136

template <bool EPI, int MB>
__device__ __forceinline__ void tc_gemm(
    const __half* __restrict__ W, const __half* __restrict__ X,
    void* __restrict__ Cout, const float* __restrict__ bias,
    const float* __restrict__ R, int m0, int n0)
{
    constexpr int MT = MB / 32;                    // m-frags per warp (4 or 2)
    constexpr int ASZ = MB * APITCH * 2;           // A stage bytes
    constexpr int STG = ASZ + 32 * BPITCH * 2;     // stage bytes
    extern __shared__ char smem[];
    const int tid = threadIdx.x;
    const int lane = tid & 31, wid = tid >> 5;
    const int wm = (wid & 1) * (MB / 2), wn = (wid >> 1) * 32;
    const uint32_t sb = smem_u32(smem);

    float c[MT][4][4];
#pragma unroll
    for (int a = 0; a < MT; a++)
#pragma unroll
        for (int b = 0; b < 4; b++)
#pragma unroll
            for (int d = 0; d < 4; d++) c[a][b][d] = 0.f;

    auto stage = [&](int i) {
        const int kt = i * 32;
        const uint32_t as = sb + (uint32_t)(i % 3) * STG;
        const uint32_t bs = as + (uint32_t)ASZ;
#pragma unroll
        for (int t = 0; t < MB / 64; t++) {
            const int idx = t * 256 + tid;
            const int row = idx >> 2, ch = idx & 3;
            const __half* src = W + (size_t)(m0 + row) * CC + kt + ch * 8;
            const int sz = (m0 + row < CC) ? 16 : 0;
            CP_ASYNC(as + (uint32_t)(row * (APITCH * 2) + ch * 16), src, sz);
        }
#pragma unroll
        for (int t = 0; t < 2; t++) {
            const int idx = t * 256 + tid;
            const int k = idx >> 4, nc = idx & 15;
            const __half* src = X + (size_t)(kt + k) * SPATIAL + n0 + nc * 8;
            CP_ASYNC(bs + (uint32_t)(k * (BPITCH * 2) + nc * 16), src, 16);
        }
        CP_COMMIT();
    };

    stage(0);
    stage(1);

    for (int i = 0; i < 10; i++) {
        if (i < 8) asm volatile("cp.async.wait_group 1;" ::: "memory");
        else       asm volatile("cp.async.wait_group 0;" ::: "memory");
        __syncthreads();
        if (i + 2 < 10) stage(i + 2);

        const uint32_t as = sb + (uint32_t)(i % 3) * STG;
        const uint32_t bs = as + (uint32_t)ASZ;

#pragma unroll
        for (int ks = 0; ks < 2; ks++) {
            uint32_t af[MT][4], bf[2][4];
#pragma unroll
            for (int mt = 0; mt < MT; mt++) {
                const uint32_t addr = as +
                    (uint32_t)((wm + mt * 16 + (lane & 15)) * (APITCH * 2) +
                               (lane >> 4) * 16 + ks * 32);
                ldsm4(af[mt], addr);
            }
#pragma unroll
            for (int nb = 0; nb < 2; nb++) {
                const uint32_t addr = bs +
                    (uint32_t)((ks * 16 + (lane & 15)) * (BPITCH * 2) +
                               (wn + nb * 16 + (lane >> 4) * 8) * 2);
                ldsm4t(bf[nb], addr);
            }
#pragma unroll
            for (int nt = 0; nt < 4; nt++) {
                const uint32_t b0 = bf[nt >> 1][(nt & 1) * 2];
                const uint32_t b1 = bf[nt >> 1][(nt & 1) * 2 + 1];
#pragma unroll
                for (int mt = 0; mt < MT; mt++)
                    mma16(c[mt][nt], af[mt], b0, b1);
            }
        }
        __syncthreads();
    }

    // ---- epilogue ----
#pragma unroll
    for (int mt = 0; mt < MT; mt++) {
#pragma unroll
        for (int nt = 0; nt < 4; nt++) {
            const int r0 = m0 + wm + mt * 16 + (lane >> 2);
            const int col = n0 + wn + nt * 8 + (lane & 3) * 2;
            if (EPI) {
                float* C = (float*)Cout;
                if (r0 < CC) {
                    const size_t o0 = (size_t)r0 * SPATIAL + col;
                    const float bb = bias[r0];
                    const float2 x0 = *(const float2*)(R + o0);
                    *(float2*)(C + o0) = make_float2(c[mt][nt][0] + bb + x0.x,
                                                     c[mt][nt][1] + bb + x0.y);
                }
                if (r0 + 8 < CC) {
                    const size_t o1 = (size_t)(r0 + 8) * SPATIAL + col;
                    const float bb = bias[r0 + 8];
                    const float2 x1 = *(const float2*)(R + o1);
                    *(float2*)(C + o1) = make_float2(c[mt][nt][2] + bb + x1.x,
                                                     c[mt][nt][3] + bb + x1.y);
                }
            } else {
                __half* C = (__half*)Cout;
                if (r0 < CC) {
                    *(__half2*)(C + (size_t)r0 * SPATIAL + col) =
                        __floats2half2_rn(c[mt][nt][0], c[mt][nt][1]);
                }
                if (r0 + 8 < CC) {
                    *(__half2*)(C + (size_t)(r0 + 8) * SPATIAL + col) =
                        __floats2half2_rn(c[mt][nt][2], c[mt][nt][3]);
                }
            }
        }
    }
}

#define STAGE128 (128 * APITCH * 2 + 32 * BPITCH * 2)   // 18944
#define STAGE64  (64 * APITCH * 2 + 32 * BPITCH * 2)    // 13824

__global__ __launch_bounds__(256, 2) void qkv_tc(
    const __half* __restrict__ Wh, const __half* __restrict__ Xh,
    __half* __restrict__ out)
{
    const int slab = blockIdx.z;
    const int wsel = blockIdx.y / 3, mt = blockIdx.y % 3;
    tc_gemm<false, 128>(Wh + (size_t)wsel * CC * CC, Xh + (size_t)slab * SLAB,
                        out + (size_t)wsel * NELEM + (size_t)slab * SLAB,
                        nullptr, nullptr, mt * 128, blockIdx.x * 128);
}

__global__ __launch_bounds__(256, 3) void o_tc(
    const __half* __restrict__ Wh, const __half* __restrict__ O,
    const float* __restrict__ bo, const float* __restrict__ X,
    float* __restrict__ out)
{
    const int slab = blockIdx.z;
    tc_gemm<true, 64>(Wh + 3ull * CC * CC, O + (size_t)slab * SLAB,
                      out + (size_t)slab * SLAB, bo, X + (size_t)slab * SLAB,
                      blockIdx.y * 64, blockIdx.x * 128);
}

// ================= Attention (round-10, known good) =================
#define J2 (DH / 4)   // 10 quad-groups

__global__ __launch_bounds__(256, 2) void attn_kernel(
    const __half* __restrict__ Qg, const __half* __restrict__ Kg,
    const __half* __restrict__ Vg, __half* __restrict__ Og,
    const float* __restrict__ relk, const float* __restrict__ relv)
{
    extern __shared__ char smc[];
    uint2* Kp = (uint2*)smc;                    // 16*10*32 uint2 = 40960B
    uint2* Vp = Kp + TT * J2 * 32;              // 40960B
    uint2* Rkp = Vp + TT * J2 * 32;             // 2640B
    uint2* Rvp = Rkp + 33 * J2;                 // 2640B  (total 87200B)

    const int b = blockIdx.z;
    const int h = blockIdx.y;
    const int s0 = blockIdx.x * 32;
    const int tid = threadIdx.x;

    __half* Ksh = (__half*)Kp;
    __half* Vsh = (__half*)Vp;
    for (int i = tid; i < TT * DH * 4; i += 256) {
        const int row = i >> 2;
        const int ch = (i & 3) * 8;
        const int f = row / DH, dd = row - f * DH;
        const size_t g =
            ((size_t)((b * TT + f) * CC + h * DH + dd)) * SPATIAL + s0 + ch;
        uint4 kk = *(const uint4*)(Kg + g);
        uint4 vv = *(const uint4*)(Vg + g);
        __half kh[8], vh[8];
        *(uint4*)kh = kk;
        *(uint4*)vh = vv;
        const int wb = (f * J2 + (dd >> 2)) * 32;
        const int e0 = dd & 3;
#pragma unroll
        for (int e = 0; e < 8; e++) {
            const int w = (wb + ch + e) * 4 + e0;
            Ksh[w] = kh[e];
            Vsh[w] = vh[e];
        }
    }
    __half* Rkh = (__half*)Rkp;
    __half* Rvh = (__half*)Rvp;
    for (int i = tid; i < 33 * DH; i += 256) {
        Rkh[i] = __float2half_rn(relk[i]);
        Rvh[i] = __float2half_rn(relv[i]);
    }
    __syncthreads();

    const int sl = tid & 31;
    const int tg = tid >> 5;
    const float scale = 0.15811388300841898f;  // 40^-0.5

    for (int rep = 0; rep < 2; rep++) {
        const int t = rep ? (15 - tg) : tg;    // warp-uniform
        const size_t base =
            ((size_t)((b * TT + t) * CC + h * DH)) * SPATIAL + s0 + sl;

        float qo[DH];
#pragma unroll
        for (int dd = 0; dd < DH; dd++)
            qo[dd] = __half2float(Qg[base + (size_t)dd * SPATIAL]) * scale;

        float sim[TT];
        float mx = -1e30f;
#pragma unroll
        for (int sp = 0; sp < TT; sp++) {
            if (sp > t) break;                 // warp-uniform
            const uint2* kp = Kp + (sp * J2) * 32 + sl;
            const uint2* rp = Rkp + (sp - t + TT) * J2;
            float p0 = 0.f, p1 = 0.f, p2 = 0.f, p3 = 0.f;
#pragma unroll
            for (int j = 0; j < J2; j++) {
                const uint2 kv = kp[j * 32];
                const uint2 rv = rp[j];
                const float2 f0 = __half22float2(__hadd2(u2h2(kv.x), u2h2(rv.x)));
                const float2 f1 = __half22float2(__hadd2(u2h2(kv.y), u2h2(rv.y)));
                p0 = fmaf(qo[4 * j],     f0.x, p0);
                p1 = fmaf(qo[4 * j + 1], f0.y, p1);
                p2 = fmaf(qo[4 * j + 2], f1.x, p2);
                p3 = fmaf(qo[4 * j + 3], f1.y, p3);
            }
            const float acc = (p0 + p1) + (p2 + p3);
            sim[sp] = acc;
            mx = fmaxf(mx, acc);
        }
        float den = 0.f;
#pragma unroll
        for (int sp = 0; sp < TT; sp++) {
            if (sp > t) break;
            const float e = __expf(sim[sp] - mx);
            sim[sp] = e;
            den += e;
        }
        const float inv = 1.f / den;

#pragma unroll
        for (int dd = 0; dd < DH; dd++) qo[dd] = 0.f;
#pragma unroll
        for (int sp = 0; sp < TT; sp++) {
            if (sp > t) break;
            const float a = sim[sp];
            const uint2* vp = Vp + (sp * J2) * 32 + sl;
            const uint2* rp = Rvp + (sp - t + TT) * J2;
#pragma unroll
            for (int j = 0; j < J2; j++) {
                const uint2 vv = vp[j * 32];
                const uint2 rv = rp[j];
                const float2 f0 = __half22float2(__hadd2(u2h2(vv.x), u2h2(rv.x)));
                const float2 f1 = __half22float2(__hadd2(u2h2(vv.y), u2h2(rv.y)));
                qo[4 * j]     = fmaf(a, f0.x, qo[4 * j]);
                qo[4 * j + 1] = fmaf(a, f0.y, qo[4 * j + 1]);
                qo[4 * j + 2] = fmaf(a, f1.x, qo[4 * j + 2]);
                qo[4 * j + 3] = fmaf(a, f1.y, qo[4 * j + 3]);
            }
        }
#pragma unroll
        for (int dd = 0; dd < DH; dd++)
            Og[base + (size_t)dd * SPATIAL] = __float2half_rn(qo[dd] * inv);
    }
}

// ================= launch =================
extern "C" void kernel_launch(void* const* d_in, const int* in_sizes, int n_in,
                              void* d_out, int out_size) {
    const float* x  = (const float*)d_in[0];
    const float* Wq = (const float*)d_in[1];
    const float* Wk = (const float*)d_in[2];
    const float* Wv = (const float*)d_in[3];
    const float* Wo = (const float*)d_in[4];
    const float* bo = (const float*)d_in[5];
    const float* rk = (const float*)d_in[6];
    const float* rv = (const float*)d_in[7];
    float* out = (float*)d_out;

    __half* hb = nullptr;
    cudaGetSymbolAddress((void**)&hb, g_hbuf);
    __half* Q  = hb;
    __half* K  = hb + 1ull * NELEM;
    __half* V  = hb + 2ull * NELEM;
    __half* O  = hb + 3ull * NELEM;
    __half* Xh = hb + 4ull * NELEM;
    __half* Wh = hb + 5ull * NELEM;

    cvt_all<<<XB + WB, 256>>>(x, Wq, Wk, Wv, Wo, Xh, Wh);

    cudaFuncSetAttribute((const void*)qkv_tc,
                         cudaFuncAttributeMaxDynamicSharedMemorySize, 3 * STAGE128);
    cudaFuncSetAttribute((const void*)o_tc,
                         cudaFuncAttributeMaxDynamicSharedMemorySize, 3 * STAGE64);

    qkv_tc<<<dim3(SPATIAL / 128, 9, NSLAB), 256, 3 * STAGE128>>>(Wh, Xh, hb);

    const int asmb = 87200;
    cudaFuncSetAttribute((const void*)attn_kernel,
                         cudaFuncAttributeMaxDynamicSharedMemorySize, asmb);
    attn_kernel<<<dim3(SPATIAL / 32, HEADS, 4), 256, asmb>>>(Q, K, V, O, rk, rv);

    o_tc<<<dim3(SPATIAL / 128, CC / 64, NSLAB), 256, 3 * STAGE64>>>(Wh, O, bo, x, out);
}

// round 12
// speedup vs baseline: 1.1925x; 1.0508x over previous
#include <cuda_runtime.h>
#include <cuda_fp16.h>
#include <cstdint>
#include <cstddef>

#define TT 16
#define HEADS 8
#define DH 40
#define CC 320
#define SPATIAL 1024
#define NSLAB 64
#define SLAB (CC * SPATIAL)
#define NELEM (1ull * NSLAB * SLAB)   // 20,971,520

// fp16 scratch: Q,K,V,O, Xh (5 x NELEM) + 4 converted W matrices
__device__ __half g_hbuf[5ull * NELEM + 4ull * CC * CC];

// ================= helpers =================
__device__ __forceinline__ uint32_t smem_u32(const void* p) {
    uint32_t a;
    asm("{ .reg .u64 t; cvta.to.shared.u64 t, %1; cvt.u32.u64 %0, t; }"
        : "=r"(a) : "l"(p));
    return a;
}
__device__ __forceinline__ void ldsm4(uint32_t* r, uint32_t a) {
    asm volatile("ldmatrix.sync.aligned.m8n8.x4.shared.b16 {%0,%1,%2,%3}, [%4];"
                 : "=r"(r[0]), "=r"(r[1]), "=r"(r[2]), "=r"(r[3]) : "r"(a));
}
__device__ __forceinline__ void ldsm4t(uint32_t* r, uint32_t a) {
    asm volatile("ldmatrix.sync.aligned.m8n8.x4.trans.shared.b16 {%0,%1,%2,%3}, [%4];"
                 : "=r"(r[0]), "=r"(r[1]), "=r"(r[2]), "=r"(r[3]) : "r"(a));
}
__device__ __forceinline__ void mma16(float* c, const uint32_t* a,
                                      uint32_t b0, uint32_t b1) {
    asm volatile(
        "mma.sync.aligned.m16n8k16.row.col.f32.f16.f16.f32 "
        "{%0,%1,%2,%3},{%4,%5,%6,%7},{%8,%9},{%0,%1,%2,%3};"
        : "+f"(c[0]), "+f"(c[1]), "+f"(c[2]), "+f"(c[3])
        : "r"(a[0]), "r"(a[1]), "r"(a[2]), "r"(a[3]), "r"(b0), "r"(b1));
}
#define CP_ASYNC(dst, src, sz) \
    asm volatile("cp.async.cg.shared.global [%0], [%1], 16, %2;" \
                 :: "r"(dst), "l"(src), "r"(sz))
#define CP_COMMIT() asm volatile("cp.async.commit_group;" ::: "memory")

__device__ __forceinline__ __half2 u2h2(uint32_t u) {
    __half2 h; *(uint32_t*)&h = u; return h;
}

// ================= fused conversion kernel =================
#define XB ((unsigned)(NELEM / 2048))        // 10240
#define WB ((unsigned)(4 * CC * CC / 2048))  // 200

__global__ __launch_bounds__(256) void cvt_all(
    const float* __restrict__ x,
    const float* __restrict__ Wq, const float* __restrict__ Wk,
    const float* __restrict__ Wv, const float* __restrict__ Wo,
    __half* __restrict__ xh, __half* __restrict__ wh)
{
    const unsigned bx = blockIdx.x;
    const float* src;
    __half* dst;
    size_t i;
    if (bx < XB) {
        i = ((size_t)bx * 256 + threadIdx.x) * 8;
        src = x; dst = xh;
    } else {
        i = ((size_t)(bx - XB) * 256 + threadIdx.x) * 8;   // < 409600
        const size_t wsz = (size_t)CC * CC;
        const int z = (int)(i / wsz);
        src = (z == 0) ? Wq : (z == 1) ? Wk : (z == 2) ? Wv : Wo;
        src -= z * wsz;
        dst = wh;
    }
    float4 a = *(const float4*)(src + i);
    float4 b = *(const float4*)(src + i + 4);
    __half2 h[4] = { __floats2half2_rn(a.x, a.y), __floats2half2_rn(a.z, a.w),
                     __floats2half2_rn(b.x, b.y), __floats2half2_rn(b.z, b.w) };
    *(uint4*)(dst + i) = *(uint4*)h;
}

// ================= fp16 tensor-core GEMM =================
// MB=64 rows per CTA (exact 5x64=320, no zero-row mma), BN cols, BK=32, K=320.
// 8 warps: (2m x 4n), warp tile 32 x (BN/4). 3-stage cp.async ring.
#define APITCH 40

template <bool EPI, int BN>
__device__ __forceinline__ void tc_gemm(
    const __half* __restrict__ W, const __half* __restrict__ X,
    void* __restrict__ Cout, const float* __restrict__ bias,
    const float* __restrict__ R, int m0, int n0)
{
    constexpr int BP  = BN + 8;                  // B pitch (halves)
    constexpr int NB  = BN / 64;                 // ldsmt per warp per ks
    constexpr int NT  = BN / 32;                 // 8-wide n-frags per warp
    constexpr int ASZ = 64 * APITCH * 2;         // 5120 B
    constexpr int STG = ASZ + 32 * BP * 2;

    extern __shared__ char smem[];
    const int tid = threadIdx.x;
    const int lane = tid & 31, wid = tid >> 5;
    const int wm = (wid & 1) * 32, wn = (wid >> 1) * (BN / 4);
    const uint32_t sb = smem_u32(smem);

    float c[2][NT][4];
#pragma unroll
    for (int a = 0; a < 2; a++)
#pragma unroll
        for (int b = 0; b < NT; b++)
#pragma unroll
            for (int d = 0; d < 4; d++) c[a][b][d] = 0.f;

    auto stage = [&](int i) {
        const int kt = i * 32;
        const uint32_t as = sb + (uint32_t)(i % 3) * STG;
        const uint32_t bs = as + (uint32_t)ASZ;
        {   // A: 64 rows x 32 halves = 256 x 16B (1 chunk/thread)
            const int row = tid >> 2, ch = tid & 3;
            const __half* src = W + (size_t)(m0 + row) * CC + kt + ch * 8;
            CP_ASYNC(as + (uint32_t)(row * (APITCH * 2) + ch * 16), src, 16);
        }
#pragma unroll
        for (int t = 0; t < BN / 64; t++) {   // B: 32 x BN halves
            const int idx = t * 256 + tid;
            const int k = idx / (BN / 8), nc = idx % (BN / 8);
            const __half* src = X + (size_t)(kt + k) * SPATIAL + n0 + nc * 8;
            CP_ASYNC(bs + (uint32_t)(k * (BP * 2) + nc * 16), src, 16);
        }
        CP_COMMIT();
    };

    stage(0);
    stage(1);

    for (int i = 0; i < 10; i++) {
        if (i < 8) asm volatile("cp.async.wait_group 1;" ::: "memory");
        else       asm volatile("cp.async.wait_group 0;" ::: "memory");
        __syncthreads();
        if (i + 2 < 10) stage(i + 2);

        const uint32_t as = sb + (uint32_t)(i % 3) * STG;
        const uint32_t bs = as + (uint32_t)ASZ;

#pragma unroll
        for (int ks = 0; ks < 2; ks++) {
            uint32_t af[2][4], bf[NB][4];
#pragma unroll
            for (int mt = 0; mt < 2; mt++) {
                const uint32_t addr = as +
                    (uint32_t)((wm + mt * 16 + (lane & 15)) * (APITCH * 2) +
                               (lane >> 4) * 16 + ks * 32);
                ldsm4(af[mt], addr);
            }
#pragma unroll
            for (int nb = 0; nb < NB; nb++) {
                const uint32_t addr = bs +
                    (uint32_t)((ks * 16 + (lane & 15)) * (BP * 2) +
                               (wn + nb * 16 + (lane >> 4) * 8) * 2);
                ldsm4t(bf[nb], addr);
            }
#pragma unroll
            for (int nt = 0; nt < NT; nt++) {
                const uint32_t b0 = bf[nt >> 1][(nt & 1) * 2];
                const uint32_t b1 = bf[nt >> 1][(nt & 1) * 2 + 1];
                mma16(c[0][nt], af[0], b0, b1);
                mma16(c[1][nt], af[1], b0, b1);
            }
        }
        __syncthreads();
    }

    // ---- epilogue (M exact: no bounds checks) ----
#pragma unroll
    for (int mt = 0; mt < 2; mt++) {
#pragma unroll
        for (int nt = 0; nt < NT; nt++) {
            const int r0 = m0 + wm + mt * 16 + (lane >> 2);
            const int col = n0 + wn + nt * 8 + (lane & 3) * 2;
            const size_t o0 = (size_t)r0 * SPATIAL + col;
            const size_t o1 = o0 + 8ull * SPATIAL;
            if (EPI) {
                float* C = (float*)Cout;
                const float b0v = bias[r0], b1v = bias[r0 + 8];
                const float2 x0 = *(const float2*)(R + o0);
                const float2 x1 = *(const float2*)(R + o1);
                *(float2*)(C + o0) = make_float2(c[mt][nt][0] + b0v + x0.x,
                                                 c[mt][nt][1] + b0v + x0.y);
                *(float2*)(C + o1) = make_float2(c[mt][nt][2] + b1v + x1.x,
                                                 c[mt][nt][3] + b1v + x1.y);
            } else {
                __half* C = (__half*)Cout;
                *(__half2*)(C + o0) =
                    __floats2half2_rn(c[mt][nt][0], c[mt][nt][1]);
                *(__half2*)(C + o1) =
                    __floats2half2_rn(c[mt][nt][2], c[mt][nt][3]);
            }
        }
    }
}

#define STG_Q (64 * APITCH * 2 + 32 * (128 + 8) * 2)   // 13824
#define STG_O (64 * APITCH * 2 + 32 * (256 + 8) * 2)   // 22016

__global__ __launch_bounds__(256, 3) void qkv_tc(
    const __half* __restrict__ Wh, const __half* __restrict__ Xh,
    __half* __restrict__ out)
{
    const int slab = blockIdx.z;
    const int wsel = blockIdx.y / 5, mt = blockIdx.y % 5;
    tc_gemm<false, 128>(Wh + (size_t)wsel * CC * CC, Xh + (size_t)slab * SLAB,
                        out + (size_t)wsel * NELEM + (size_t)slab * SLAB,
                        nullptr, nullptr, mt * 64, blockIdx.x * 128);
}

__global__ __launch_bounds__(256, 2) void o_tc(
    const __half* __restrict__ Wh, const __half* __restrict__ O,
    const float* __restrict__ bo, const float* __restrict__ X,
    float* __restrict__ out)
{
    const int slab = blockIdx.z;
    tc_gemm<true, 256>(Wh + 3ull * CC * CC, O + (size_t)slab * SLAB,
                       out + (size_t)slab * SLAB, bo, X + (size_t)slab * SLAB,
                       blockIdx.y * 64, blockIdx.x * 256);
}

// ================= Attention (uint4 smem loads, 5-iter j-loop) =================
#define J4 (DH / 8)   // 5 octet-groups

__global__ __launch_bounds__(256, 2) void attn_kernel(
    const __half* __restrict__ Qg, const __half* __restrict__ Kg,
    const __half* __restrict__ Vg, __half* __restrict__ Og,
    const float* __restrict__ relk, const float* __restrict__ relv)
{
    extern __shared__ char smc[];
    uint4* Kp = (uint4*)smc;                    // 16*5*32 uint4 = 40960B
    uint4* Vp = Kp + TT * J4 * 32;              // 40960B
    uint4* Rkp = Vp + TT * J4 * 32;             // 33*5 uint4 = 2640B
    uint4* Rvp = Rkp + 33 * J4;                 // 2640B  (total 87200B)

    const int b = blockIdx.z;
    const int h = blockIdx.y;
    const int s0 = blockIdx.x * 32;
    const int tid = threadIdx.x;

    __half* Ksh = (__half*)Kp;
    __half* Vsh = (__half*)Vp;
    for (int i = tid; i < TT * DH * 4; i += 256) {
        const int row = i >> 2;                  // (f, dd)
        const int ch = (i & 3) * 8;              // spatial chunk base
        const int f = row / DH, dd = row - f * DH;
        const size_t g =
            ((size_t)((b * TT + f) * CC + h * DH + dd)) * SPATIAL + s0 + ch;
        uint4 kk = *(const uint4*)(Kg + g);
        uint4 vv = *(const uint4*)(Vg + g);
        __half kh[8], vh[8];
        *(uint4*)kh = kk;
        *(uint4*)vh = vv;
        const int wb = (f * J4 + (dd >> 3)) * 32;
        const int e0 = dd & 7;
#pragma unroll
        for (int e = 0; e < 8; e++) {
            const int w = (wb + ch + e) * 8 + e0;
            Ksh[w] = kh[e];
            Vsh[w] = vh[e];
        }
    }
    __half* Rkh = (__half*)Rkp;
    __half* Rvh = (__half*)Rvp;
    for (int i = tid; i < 33 * DH; i += 256) {
        Rkh[i] = __float2half_rn(relk[i]);
        Rvh[i] = __float2half_rn(relv[i]);
    }
    __syncthreads();

    const int sl = tid & 31;
    const int tg = tid >> 5;
    const float scale = 0.15811388300841898f;  // 40^-0.5

    for (int rep = 0; rep < 2; rep++) {
        const int t = rep ? (15 - tg) : tg;    // warp-uniform
        const size_t base =
            ((size_t)((b * TT + t) * CC + h * DH)) * SPATIAL + s0 + sl;

        float qo[DH];
#pragma unroll
        for (int dd = 0; dd < DH; dd++)
            qo[dd] = __half2float(Qg[base + (size_t)dd * SPATIAL]) * scale;

        float sim[TT];
        float mx = -1e30f;
#pragma unroll
        for (int sp = 0; sp < TT; sp++) {
            if (sp > t) break;                 // warp-uniform
            const uint4* kp = Kp + (sp * J4) * 32 + sl;
            const uint4* rp = Rkp + (sp - t + TT) * J4;
            float p0 = 0.f, p1 = 0.f, p2 = 0.f, p3 = 0.f;
#pragma unroll
            for (int j = 0; j < J4; j++) {
                const uint4 kv = kp[j * 32];
                const uint4 rv = rp[j];
                const float2 f0 = __half22float2(__hadd2(u2h2(kv.x), u2h2(rv.x)));
                const float2 f1 = __half22float2(__hadd2(u2h2(kv.y), u2h2(rv.y)));
                const float2 f2 = __half22float2(__hadd2(u2h2(kv.z), u2h2(rv.z)));
                const float2 f3 = __half22float2(__hadd2(u2h2(kv.w), u2h2(rv.w)));
                p0 = fmaf(qo[8 * j],     f0.x, p0);
                p1 = fmaf(qo[8 * j + 1], f0.y, p1);
                p2 = fmaf(qo[8 * j + 2], f1.x, p2);
                p3 = fmaf(qo[8 * j + 3], f1.y, p3);
                p0 = fmaf(qo[8 * j + 4], f2.x, p0);
                p1 = fmaf(qo[8 * j + 5], f2.y, p1);
                p2 = fmaf(qo[8 * j + 6], f3.x, p2);
                p3 = fmaf(qo[8 * j + 7], f3.y, p3);
            }
            const float acc = (p0 + p1) + (p2 + p3);
            sim[sp] = acc;
            mx = fmaxf(mx, acc);
        }
        float den = 0.f;
#pragma unroll
        for (int sp = 0; sp < TT; sp++) {
            if (sp > t) break;
            const float e = __expf(sim[sp] - mx);
            sim[sp] = e;
            den += e;
        }
        const float inv = 1.f / den;

#pragma unroll
        for (int dd = 0; dd < DH; dd++) qo[dd] = 0.f;
#pragma unroll
        for (int sp = 0; sp < TT; sp++) {
            if (sp > t) break;
            const float a = sim[sp] * inv;     // inv folded into weight
            const uint4* vp = Vp + (sp * J4) * 32 + sl;
            const uint4* rp = Rvp + (sp - t + TT) * J4;
#pragma unroll
            for (int j = 0; j < J4; j++) {
                const uint4 vv = vp[j * 32];
                const uint4 rv = rp[j];
                const float2 f0 = __half22float2(__hadd2(u2h2(vv.x), u2h2(rv.x)));
                const float2 f1 = __half22float2(__hadd2(u2h2(vv.y), u2h2(rv.y)));
                const float2 f2 = __half22float2(__hadd2(u2h2(vv.z), u2h2(rv.z)));
                const float2 f3 = __half22float2(__hadd2(u2h2(vv.w), u2h2(rv.w)));
                qo[8 * j]     = fmaf(a, f0.x, qo[8 * j]);
                qo[8 * j + 1] = fmaf(a, f0.y, qo[8 * j + 1]);
                qo[8 * j + 2] = fmaf(a, f1.x, qo[8 * j + 2]);
                qo[8 * j + 3] = fmaf(a, f1.y, qo[8 * j + 3]);
                qo[8 * j + 4] = fmaf(a, f2.x, qo[8 * j + 4]);
                qo[8 * j + 5] = fmaf(a, f2.y, qo[8 * j + 5]);
                qo[8 * j + 6] = fmaf(a, f3.x, qo[8 * j + 6]);
                qo[8 * j + 7] = fmaf(a, f3.y, qo[8 * j + 7]);
            }
        }
#pragma unroll
        for (int dd = 0; dd < DH; dd++)
            Og[base + (size_t)dd * SPATIAL] = __float2half_rn(qo[dd]);
    }
}

// ================= launch =================
extern "C" void kernel_launch(void* const* d_in, const int* in_sizes, int n_in,
                              void* d_out, int out_size) {
    const float* x  = (const float*)d_in[0];
    const float* Wq = (const float*)d_in[1];
    const float* Wk = (const float*)d_in[2];
    const float* Wv = (const float*)d_in[3];
    const float* Wo = (const float*)d_in[4];
    const float* bo = (const float*)d_in[5];
    const float* rk = (const float*)d_in[6];
    const float* rv = (const float*)d_in[7];
    float* out = (float*)d_out;

    __half* hb = nullptr;
    cudaGetSymbolAddress((void**)&hb, g_hbuf);
    __half* Q  = hb;
    __half* K  = hb + 1ull * NELEM;
    __half* V  = hb + 2ull * NELEM;
    __half* O  = hb + 3ull * NELEM;
    __half* Xh = hb + 4ull * NELEM;
    __half* Wh = hb + 5ull * NELEM;

    cvt_all<<<XB + WB, 256>>>(x, Wq, Wk, Wv, Wo, Xh, Wh);

    cudaFuncSetAttribute((const void*)qkv_tc,
                         cudaFuncAttributeMaxDynamicSharedMemorySize, 3 * STG_Q);
    cudaFuncSetAttribute((const void*)o_tc,
                         cudaFuncAttributeMaxDynamicSharedMemorySize, 3 * STG_O);

    qkv_tc<<<dim3(SPATIAL / 128, 15, NSLAB), 256, 3 * STG_Q>>>(Wh, Xh, hb);

    const int asmb = 87200;
    cudaFuncSetAttribute((const void*)attn_kernel,
                         cudaFuncAttributeMaxDynamicSharedMemorySize, asmb);
    attn_kernel<<<dim3(SPATIAL / 32, HEADS, 4), 256, asmb>>>(Q, K, V, O, rk, rv);

    o_tc<<<dim3(SPATIAL / 256, CC / 64, NSLAB), 256, 3 * STG_O>>>(Wh, O, bo, x, out);
}

// round 13
// speedup vs baseline: 1.2135x; 1.0176x over previous
#include <cuda_runtime.h>
#include <cuda_fp16.h>
#include <cstdint>
#include <cstddef>

#define TT 16
#define HEADS 8
#define DH 40
#define CC 320
#define SPATIAL 1024
#define NSLAB 64
#define SLAB (CC * SPATIAL)
#define NELEM (1ull * NSLAB * SLAB)   // 20,971,520

// fp16 scratch: Q,K,V,O, Xh (5 x NELEM) + 4 converted W matrices
__device__ __half g_hbuf[5ull * NELEM + 4ull * CC * CC];

// ================= helpers =================
__device__ __forceinline__ uint32_t smem_u32(const void* p) {
    uint32_t a;
    asm("{ .reg .u64 t; cvta.to.shared.u64 t, %1; cvt.u32.u64 %0, t; }"
        : "=r"(a) : "l"(p));
    return a;
}
__device__ __forceinline__ void ldsm4(uint32_t* r, uint32_t a) {
    asm volatile("ldmatrix.sync.aligned.m8n8.x4.shared.b16 {%0,%1,%2,%3}, [%4];"
                 : "=r"(r[0]), "=r"(r[1]), "=r"(r[2]), "=r"(r[3]) : "r"(a));
}
__device__ __forceinline__ void ldsm4t(uint32_t* r, uint32_t a) {
    asm volatile("ldmatrix.sync.aligned.m8n8.x4.trans.shared.b16 {%0,%1,%2,%3}, [%4];"
                 : "=r"(r[0]), "=r"(r[1]), "=r"(r[2]), "=r"(r[3]) : "r"(a));
}
__device__ __forceinline__ void mma16(float* c, const uint32_t* a,
                                      uint32_t b0, uint32_t b1) {
    asm volatile(
        "mma.sync.aligned.m16n8k16.row.col.f32.f16.f16.f32 "
        "{%0,%1,%2,%3},{%4,%5,%6,%7},{%8,%9},{%0,%1,%2,%3};"
        : "+f"(c[0]), "+f"(c[1]), "+f"(c[2]), "+f"(c[3])
        : "r"(a[0]), "r"(a[1]), "r"(a[2]), "r"(a[3]), "r"(b0), "r"(b1));
}
#define CP_ASYNC(dst, src, sz) \
    asm volatile("cp.async.cg.shared.global [%0], [%1], 16, %2;" \
                 :: "r"(dst), "l"(src), "r"(sz))
#define CP_COMMIT() asm volatile("cp.async.commit_group;" ::: "memory")

__device__ __forceinline__ __half2 u2h2(uint32_t u) {
    __half2 h; *(uint32_t*)&h = u; return h;
}

// ================= fused conversion kernel =================
#define XB ((unsigned)(NELEM / 2048))        // 10240
#define WB ((unsigned)(4 * CC * CC / 2048))  // 200

__global__ __launch_bounds__(256) void cvt_all(
    const float* __restrict__ x,
    const float* __restrict__ Wq, const float* __restrict__ Wk,
    const float* __restrict__ Wv, const float* __restrict__ Wo,
    __half* __restrict__ xh, __half* __restrict__ wh)
{
    const unsigned bx = blockIdx.x;
    const float* src;
    __half* dst;
    size_t i;
    if (bx < XB) {
        i = ((size_t)bx * 256 + threadIdx.x) * 8;
        src = x; dst = xh;
    } else {
        i = ((size_t)(bx - XB) * 256 + threadIdx.x) * 8;   // < 409600
        const size_t wsz = (size_t)CC * CC;
        const int z = (int)(i / wsz);
        src = (z == 0) ? Wq : (z == 1) ? Wk : (z == 2) ? Wv : Wo;
        src -= z * wsz;
        dst = wh;
    }
    float4 a = *(const float4*)(src + i);
    float4 b = *(const float4*)(src + i + 4);
    __half2 h[4] = { __floats2half2_rn(a.x, a.y), __floats2half2_rn(a.z, a.w),
                     __floats2half2_rn(b.x, b.y), __floats2half2_rn(b.z, b.w) };
    *(uint4*)(dst + i) = *(uint4*)h;
}

// ================= fused QKV GEMM =================
// One CTA computes Q,K,V 64x128 tiles for (m0, n0, slab): B tile loaded once,
// reused across 3 weight matrices. 8 warps (2m x 4n), warp tile 32x32.
// smem/stage: 3 x A(64x40h = 5120B) + B(32x136h = 8704B) = 24064B; x3 stages.
#define APITCH 40
#define ASTG 5120
#define QA (3 * ASTG)            // 15360
#define QSTG (QA + 32 * 136 * 2) // 24064

__global__ __launch_bounds__(256, 2) void qkv_tc(
    const __half* __restrict__ Wh, const __half* __restrict__ Xh,
    __half* __restrict__ out)
{
    extern __shared__ char smem[];
    const int slab = blockIdx.z;
    const int m0 = blockIdx.y * 64;
    const int n0 = blockIdx.x * 128;
    const __half* X = Xh + (size_t)slab * SLAB;

    const int tid = threadIdx.x;
    const int lane = tid & 31, wid = tid >> 5;
    const int wm = (wid & 1) * 32, wn = (wid >> 1) * 32;
    const uint32_t sb = smem_u32(smem);

    float c[3][2][4][4];
#pragma unroll
    for (int w = 0; w < 3; w++)
#pragma unroll
        for (int a = 0; a < 2; a++)
#pragma unroll
            for (int b = 0; b < 4; b++)
#pragma unroll
                for (int d = 0; d < 4; d++) c[w][a][b][d] = 0.f;

    auto stage = [&](int i) {
        const int kt = i * 32;
        const uint32_t base = sb + (uint32_t)(i % 3) * QSTG;
        const int row = tid >> 2, ch = tid & 3;
#pragma unroll
        for (int w = 0; w < 3; w++) {
            const __half* src =
                Wh + (size_t)w * CC * CC + (size_t)(m0 + row) * CC + kt + ch * 8;
            CP_ASYNC(base + (uint32_t)(w * ASTG + row * (APITCH * 2) + ch * 16),
                     src, 16);
        }
#pragma unroll
        for (int t = 0; t < 2; t++) {
            const int idx = t * 256 + tid;
            const int k = idx >> 4, nc = idx & 15;
            const __half* src = X + (size_t)(kt + k) * SPATIAL + n0 + nc * 8;
            CP_ASYNC(base + (uint32_t)(QA + k * 272 + nc * 16), src, 16);
        }
        CP_COMMIT();
    };

    stage(0);
    stage(1);

    for (int i = 0; i < 10; i++) {
        if (i < 8) asm volatile("cp.async.wait_group 1;" ::: "memory");
        else       asm volatile("cp.async.wait_group 0;" ::: "memory");
        __syncthreads();
        if (i + 2 < 10) stage(i + 2);

        const uint32_t base = sb + (uint32_t)(i % 3) * QSTG;
        const uint32_t bs = base + (uint32_t)QA;

#pragma unroll
        for (int ks = 0; ks < 2; ks++) {
            uint32_t bf[2][4];
#pragma unroll
            for (int nb = 0; nb < 2; nb++) {
                const uint32_t addr = bs +
                    (uint32_t)((ks * 16 + (lane & 15)) * 272 +
                               (wn + nb * 16 + (lane >> 4) * 8) * 2);
                ldsm4t(bf[nb], addr);
            }
#pragma unroll
            for (int w = 0; w < 3; w++) {
                uint32_t af[2][4];
#pragma unroll
                for (int mt = 0; mt < 2; mt++) {
                    const uint32_t addr = base + (uint32_t)(w * ASTG +
                        (wm + mt * 16 + (lane & 15)) * (APITCH * 2) +
                        (lane >> 4) * 16 + ks * 32);
                    ldsm4(af[mt], addr);
                }
#pragma unroll
                for (int nt = 0; nt < 4; nt++) {
                    const uint32_t b0 = bf[nt >> 1][(nt & 1) * 2];
                    const uint32_t b1 = bf[nt >> 1][(nt & 1) * 2 + 1];
                    mma16(c[w][0][nt], af[0], b0, b1);
                    mma16(c[w][1][nt], af[1], b0, b1);
                }
            }
        }
        __syncthreads();
    }

    // ---- epilogue: 3 outputs ----
#pragma unroll
    for (int w = 0; w < 3; w++) {
        __half* C = out + (size_t)w * NELEM + (size_t)slab * SLAB;
#pragma unroll
        for (int mt = 0; mt < 2; mt++) {
#pragma unroll
            for (int nt = 0; nt < 4; nt++) {
                const int r0 = m0 + wm + mt * 16 + (lane >> 2);
                const int col = n0 + wn + nt * 8 + (lane & 3) * 2;
                const size_t o0 = (size_t)r0 * SPATIAL + col;
                *(__half2*)(C + o0) =
                    __floats2half2_rn(c[w][mt][nt][0], c[w][mt][nt][1]);
                *(__half2*)(C + o0 + 8ull * SPATIAL) =
                    __floats2half2_rn(c[w][mt][nt][2], c[w][mt][nt][3]);
            }
        }
    }
}

// ================= O projection (BN=256, fp16 residual) =================
#define STG_O (64 * APITCH * 2 + 32 * (256 + 8) * 2)   // 22016

__global__ __launch_bounds__(256, 2) void o_tc(
    const __half* __restrict__ Wh, const __half* __restrict__ O,
    const float* __restrict__ bo, const __half* __restrict__ Rh,
    float* __restrict__ out)
{
    constexpr int BN = 256, BP = BN + 8;
    extern __shared__ char smem[];
    const int slab = blockIdx.z;
    const int m0 = blockIdx.y * 64;
    const int n0 = blockIdx.x * BN;
    const __half* X = O + (size_t)slab * SLAB;
    const __half* R = Rh + (size_t)slab * SLAB;
    float* C = out + (size_t)slab * SLAB;
    const __half* W = Wh + 3ull * CC * CC;

    const int tid = threadIdx.x;
    const int lane = tid & 31, wid = tid >> 5;
    const int wm = (wid & 1) * 32, wn = (wid >> 1) * (BN / 4);
    const uint32_t sb = smem_u32(smem);
    constexpr int ASZ = 64 * APITCH * 2;
    constexpr int STG = ASZ + 32 * BP * 2;

    float c[2][8][4];
#pragma unroll
    for (int a = 0; a < 2; a++)
#pragma unroll
        for (int b = 0; b < 8; b++)
#pragma unroll
            for (int d = 0; d < 4; d++) c[a][b][d] = 0.f;

    auto stage = [&](int i) {
        const int kt = i * 32;
        const uint32_t as = sb + (uint32_t)(i % 3) * STG;
        const uint32_t bs = as + (uint32_t)ASZ;
        {
            const int row = tid >> 2, ch = tid & 3;
            const __half* src = W + (size_t)(m0 + row) * CC + kt + ch * 8;
            CP_ASYNC(as + (uint32_t)(row * (APITCH * 2) + ch * 16), src, 16);
        }
#pragma unroll
        for (int t = 0; t < 4; t++) {
            const int idx = t * 256 + tid;
            const int k = idx >> 5, nc = idx & 31;
            const __half* src = X + (size_t)(kt + k) * SPATIAL + n0 + nc * 8;
            CP_ASYNC(bs + (uint32_t)(k * (BP * 2) + nc * 16), src, 16);
        }
        CP_COMMIT();
    };

    stage(0);
    stage(1);

    for (int i = 0; i < 10; i++) {
        if (i < 8) asm volatile("cp.async.wait_group 1;" ::: "memory");
        else       asm volatile("cp.async.wait_group 0;" ::: "memory");
        __syncthreads();
        if (i + 2 < 10) stage(i + 2);

        const uint32_t as = sb + (uint32_t)(i % 3) * STG;
        const uint32_t bs = as + (uint32_t)ASZ;

#pragma unroll
        for (int ks = 0; ks < 2; ks++) {
            uint32_t af[2][4], bf[4][4];
#pragma unroll
            for (int mt = 0; mt < 2; mt++) {
                const uint32_t addr = as +
                    (uint32_t)((wm + mt * 16 + (lane & 15)) * (APITCH * 2) +
                               (lane >> 4) * 16 + ks * 32);
                ldsm4(af[mt], addr);
            }
#pragma unroll
            for (int nb = 0; nb < 4; nb++) {
                const uint32_t addr = bs +
                    (uint32_t)((ks * 16 + (lane & 15)) * (BP * 2) +
                               (wn + nb * 16 + (lane >> 4) * 8) * 2);
                ldsm4t(bf[nb], addr);
            }
#pragma unroll
            for (int nt = 0; nt < 8; nt++) {
                const uint32_t b0 = bf[nt >> 1][(nt & 1) * 2];
                const uint32_t b1 = bf[nt >> 1][(nt & 1) * 2 + 1];
                mma16(c[0][nt], af[0], b0, b1);
                mma16(c[1][nt], af[1], b0, b1);
            }
        }
        __syncthreads();
    }

#pragma unroll
    for (int mt = 0; mt < 2; mt++) {
#pragma unroll
        for (int nt = 0; nt < 8; nt++) {
            const int r0 = m0 + wm + mt * 16 + (lane >> 2);
            const int col = n0 + wn + nt * 8 + (lane & 3) * 2;
            const size_t o0 = (size_t)r0 * SPATIAL + col;
            const size_t o1 = o0 + 8ull * SPATIAL;
            const float b0v = bo[r0], b1v = bo[r0 + 8];
            const float2 x0 = __half22float2(*(const __half2*)(R + o0));
            const float2 x1 = __half22float2(*(const __half2*)(R + o1));
            *(float2*)(C + o0) = make_float2(c[mt][nt][0] + b0v + x0.x,
                                             c[mt][nt][1] + b0v + x0.y);
            *(float2*)(C + o1) = make_float2(c[mt][nt][2] + b1v + x1.x,
                                             c[mt][nt][3] + b1v + x1.y);
        }
    }
}

// ================= Attention (round-12, known good) =================
#define J4 (DH / 8)   // 5 octet-groups

__global__ __launch_bounds__(256, 2) void attn_kernel(
    const __half* __restrict__ Qg, const __half* __restrict__ Kg,
    const __half* __restrict__ Vg, __half* __restrict__ Og,
    const float* __restrict__ relk, const float* __restrict__ relv)
{
    extern __shared__ char smc[];
    uint4* Kp = (uint4*)smc;
    uint4* Vp = Kp + TT * J4 * 32;
    uint4* Rkp = Vp + TT * J4 * 32;
    uint4* Rvp = Rkp + 33 * J4;

    const int b = blockIdx.z;
    const int h = blockIdx.y;
    const int s0 = blockIdx.x * 32;
    const int tid = threadIdx.x;

    __half* Ksh = (__half*)Kp;
    __half* Vsh = (__half*)Vp;
    for (int i = tid; i < TT * DH * 4; i += 256) {
        const int row = i >> 2;
        const int ch = (i & 3) * 8;
        const int f = row / DH, dd = row - f * DH;
        const size_t g =
            ((size_t)((b * TT + f) * CC + h * DH + dd)) * SPATIAL + s0 + ch;
        uint4 kk = *(const uint4*)(Kg + g);
        uint4 vv = *(const uint4*)(Vg + g);
        __half kh[8], vh[8];
        *(uint4*)kh = kk;
        *(uint4*)vh = vv;
        const int wb = (f * J4 + (dd >> 3)) * 32;
        const int e0 = dd & 7;
#pragma unroll
        for (int e = 0; e < 8; e++) {
            const int w = (wb + ch + e) * 8 + e0;
            Ksh[w] = kh[e];
            Vsh[w] = vh[e];
        }
    }
    __half* Rkh = (__half*)Rkp;
    __half* Rvh = (__half*)Rvp;
    for (int i = tid; i < 33 * DH; i += 256) {
        Rkh[i] = __float2half_rn(relk[i]);
        Rvh[i] = __float2half_rn(relv[i]);
    }
    __syncthreads();

    const int sl = tid & 31;
    const int tg = tid >> 5;
    const float scale = 0.15811388300841898f;  // 40^-0.5

    for (int rep = 0; rep < 2; rep++) {
        const int t = rep ? (15 - tg) : tg;    // warp-uniform
        const size_t base =
            ((size_t)((b * TT + t) * CC + h * DH)) * SPATIAL + s0 + sl;

        float qo[DH];
#pragma unroll
        for (int dd = 0; dd < DH; dd++)
            qo[dd] = __half2float(Qg[base + (size_t)dd * SPATIAL]) * scale;

        float sim[TT];
        float mx = -1e30f;
#pragma unroll
        for (int sp = 0; sp < TT; sp++) {
            if (sp > t) break;
            const uint4* kp = Kp + (sp * J4) * 32 + sl;
            const uint4* rp = Rkp + (sp - t + TT) * J4;
            float p0 = 0.f, p1 = 0.f, p2 = 0.f, p3 = 0.f;
#pragma unroll
            for (int j = 0; j < J4; j++) {
                const uint4 kv = kp[j * 32];
                const uint4 rv = rp[j];
                const float2 f0 = __half22float2(__hadd2(u2h2(kv.x), u2h2(rv.x)));
                const float2 f1 = __half22float2(__hadd2(u2h2(kv.y), u2h2(rv.y)));
                const float2 f2 = __half22float2(__hadd2(u2h2(kv.z), u2h2(rv.z)));
                const float2 f3 = __half22float2(__hadd2(u2h2(kv.w), u2h2(rv.w)));
                p0 = fmaf(qo[8 * j],     f0.x, p0);
                p1 = fmaf(qo[8 * j + 1], f0.y, p1);
                p2 = fmaf(qo[8 * j + 2], f1.x, p2);
                p3 = fmaf(qo[8 * j + 3], f1.y, p3);
                p0 = fmaf(qo[8 * j + 4], f2.x, p0);
                p1 = fmaf(qo[8 * j + 5], f2.y, p1);
                p2 = fmaf(qo[8 * j + 6], f3.x, p2);
                p3 = fmaf(qo[8 * j + 7], f3.y, p3);
            }
            const float acc = (p0 + p1) + (p2 + p3);
            sim[sp] = acc;
            mx = fmaxf(mx, acc);
        }
        float den = 0.f;
#pragma unroll
        for (int sp = 0; sp < TT; sp++) {
            if (sp > t) break;
            const float e = __expf(sim[sp] - mx);
            sim[sp] = e;
            den += e;
        }
        const float inv = 1.f / den;

#pragma unroll
        for (int dd = 0; dd < DH; dd++) qo[dd] = 0.f;
#pragma unroll
        for (int sp = 0; sp < TT; sp++) {
            if (sp > t) break;
            const float a = sim[sp] * inv;
            const uint4* vp = Vp + (sp * J4) * 32 + sl;
            const uint4* rp = Rvp + (sp - t + TT) * J4;
#pragma unroll
            for (int j = 0; j < J4; j++) {
                const uint4 vv = vp[j * 32];
                const uint4 rv = rp[j];
                const float2 f0 = __half22float2(__hadd2(u2h2(vv.x), u2h2(rv.x)));
                const float2 f1 = __half22float2(__hadd2(u2h2(vv.y), u2h2(rv.y)));
                const float2 f2 = __half22float2(__hadd2(u2h2(vv.z), u2h2(rv.z)));
                const float2 f3 = __half22float2(__hadd2(u2h2(vv.w), u2h2(rv.w)));
                qo[8 * j]     = fmaf(a, f0.x, qo[8 * j]);
                qo[8 * j + 1] = fmaf(a, f0.y, qo[8 * j + 1]);
                qo[8 * j + 2] = fmaf(a, f1.x, qo[8 * j + 2]);
                qo[8 * j + 3] = fmaf(a, f1.y, qo[8 * j + 3]);
                qo[8 * j + 4] = fmaf(a, f2.x, qo[8 * j + 4]);
                qo[8 * j + 5] = fmaf(a, f2.y, qo[8 * j + 5]);
                qo[8 * j + 6] = fmaf(a, f3.x, qo[8 * j + 6]);
                qo[8 * j + 7] = fmaf(a, f3.y, qo[8 * j + 7]);
            }
        }
#pragma unroll
        for (int dd = 0; dd < DH; dd++)
            Og[base + (size_t)dd * SPATIAL] = __float2half_rn(qo[dd]);
    }
}

// ================= launch =================
extern "C" void kernel_launch(void* const* d_in, const int* in_sizes, int n_in,
                              void* d_out, int out_size) {
    const float* x  = (const float*)d_in[0];
    const float* Wq = (const float*)d_in[1];
    const float* Wk = (const float*)d_in[2];
    const float* Wv = (const float*)d_in[3];
    const float* Wo = (const float*)d_in[4];
    const float* bo = (const float*)d_in[5];
    const float* rk = (const float*)d_in[6];
    const float* rv = (const float*)d_in[7];
    float* out = (float*)d_out;

    __half* hb = nullptr;
    cudaGetSymbolAddress((void**)&hb, g_hbuf);
    __half* Q  = hb;
    __half* K  = hb + 1ull * NELEM;
    __half* V  = hb + 2ull * NELEM;
    __half* O  = hb + 3ull * NELEM;
    __half* Xh = hb + 4ull * NELEM;
    __half* Wh = hb + 5ull * NELEM;

    cvt_all<<<XB + WB, 256>>>(x, Wq, Wk, Wv, Wo, Xh, Wh);

    cudaFuncSetAttribute((const void*)qkv_tc,
                         cudaFuncAttributeMaxDynamicSharedMemorySize, 3 * QSTG);
    cudaFuncSetAttribute((const void*)o_tc,
                         cudaFuncAttributeMaxDynamicSharedMemorySize, 3 * STG_O);

    qkv_tc<<<dim3(SPATIAL / 128, CC / 64, NSLAB), 256, 3 * QSTG>>>(Wh, Xh, hb);

    const int asmb = 87200;
    cudaFuncSetAttribute((const void*)attn_kernel,
                         cudaFuncAttributeMaxDynamicSharedMemorySize, asmb);
    attn_kernel<<<dim3(SPATIAL / 32, HEADS, 4), 256, asmb>>>(Q, K, V, O, rk, rv);

    o_tc<<<dim3(SPATIAL / 256, CC / 64, NSLAB), 256, 3 * STG_O>>>(Wh, O, bo, Xh, out);
}

// round 15
// speedup vs baseline: 1.2205x; 1.0058x over previous
#include <cuda_runtime.h>
#include <cuda_fp16.h>
#include <cstdint>
#include <cstddef>

#define TT 16
#define HEADS 8
#define DH 40
#define CC 320
#define SPATIAL 1024
#define NSLAB 64
#define SLAB (CC * SPATIAL)
#define NELEM (1ull * NSLAB * SLAB)   // 20,971,520

// fp16 scratch: Q,K,V,O, Xh (5 x NELEM) + 4 converted W matrices
__device__ __half g_hbuf[5ull * NELEM + 4ull * CC * CC];

// ================= helpers =================
__device__ __forceinline__ uint32_t smem_u32(const void* p) {
    uint32_t a;
    asm("{ .reg .u64 t; cvta.to.shared.u64 t, %1; cvt.u32.u64 %0, t; }"
        : "=r"(a) : "l"(p));
    return a;
}
__device__ __forceinline__ void ldsm4(uint32_t* r, uint32_t a) {
    asm volatile("ldmatrix.sync.aligned.m8n8.x4.shared.b16 {%0,%1,%2,%3}, [%4];"
                 : "=r"(r[0]), "=r"(r[1]), "=r"(r[2]), "=r"(r[3]) : "r"(a));
}
__device__ __forceinline__ void ldsm4t(uint32_t* r, uint32_t a) {
    asm volatile("ldmatrix.sync.aligned.m8n8.x4.trans.shared.b16 {%0,%1,%2,%3}, [%4];"
                 : "=r"(r[0]), "=r"(r[1]), "=r"(r[2]), "=r"(r[3]) : "r"(a));
}
__device__ __forceinline__ void mma16(float* c, const uint32_t* a,
                                      uint32_t b0, uint32_t b1) {
    asm volatile(
        "mma.sync.aligned.m16n8k16.row.col.f32.f16.f16.f32 "
        "{%0,%1,%2,%3},{%4,%5,%6,%7},{%8,%9},{%0,%1,%2,%3};"
        : "+f"(c[0]), "+f"(c[1]), "+f"(c[2]), "+f"(c[3])
        : "r"(a[0]), "r"(a[1]), "r"(a[2]), "r"(a[3]), "r"(b0), "r"(b1));
}
#define CP_ASYNC(dst, src, sz) \
    asm volatile("cp.async.cg.shared.global [%0], [%1], 16, %2;" \
                 :: "r"(dst), "l"(src), "r"(sz))
#define CP_COMMIT() asm volatile("cp.async.commit_group;" ::: "memory")

__device__ __forceinline__ __half2 u2h2(uint32_t u) {
    __half2 h; *(uint32_t*)&h = u; return h;
}

// ================= fused conversion kernel =================
#define XB ((unsigned)(NELEM / 2048))        // 10240
#define WB ((unsigned)(4 * CC * CC / 2048))  // 200

__global__ __launch_bounds__(256) void cvt_all(
    const float* __restrict__ x,
    const float* __restrict__ Wq, const float* __restrict__ Wk,
    const float* __restrict__ Wv, const float* __restrict__ Wo,
    __half* __restrict__ xh, __half* __restrict__ wh)
{
    const unsigned bx = blockIdx.x;
    const float* src;
    __half* dst;
    size_t i;
    if (bx < XB) {
        i = ((size_t)bx * 256 + threadIdx.x) * 8;
        src = x; dst = xh;
    } else {
        i = ((size_t)(bx - XB) * 256 + threadIdx.x) * 8;   // < 409600
        const size_t wsz = (size_t)CC * CC;
        const int z = (int)(i / wsz);
        src = (z == 0) ? Wq : (z == 1) ? Wk : (z == 2) ? Wv : Wo;
        src -= z * wsz;
        dst = wh;
    }
    float4 a = *(const float4*)(src + i);
    float4 b = *(const float4*)(src + i + 4);
    __half2 h[4] = { __floats2half2_rn(a.x, a.y), __floats2half2_rn(a.z, a.w),
                     __floats2half2_rn(b.x, b.y), __floats2half2_rn(b.z, b.w) };
    *(uint4*)(dst + i) = *(uint4*)h;
}

// ================= fused QKV GEMM =================
// One CTA computes Q,K,V 64x128 tiles for (m0, n0, slab); B loaded once,
// reused across 3 weight matrices. 8 warps (2m x 4n), warp tile 32x32.
#define APITCH 40
#define ASTG 5120
#define QA (3 * ASTG)            // 15360
#define QSTG (QA + 32 * 136 * 2) // 24064

__global__ __launch_bounds__(256, 2) void qkv_tc(
    const __half* __restrict__ Wh, const __half* __restrict__ Xh,
    __half* __restrict__ out)
{
    extern __shared__ char smem[];
    const int slab = blockIdx.z;
    const int m0 = blockIdx.y * 64;
    const int n0 = blockIdx.x * 128;
    const __half* X = Xh + (size_t)slab * SLAB;

    const int tid = threadIdx.x;
    const int lane = tid & 31, wid = tid >> 5;
    const int wm = (wid & 1) * 32, wn = (wid >> 1) * 32;
    const uint32_t sb = smem_u32(smem);

    float c[3][2][4][4];
#pragma unroll
    for (int w = 0; w < 3; w++)
#pragma unroll
        for (int a = 0; a < 2; a++)
#pragma unroll
            for (int b = 0; b < 4; b++)
#pragma unroll
                for (int d = 0; d < 4; d++) c[w][a][b][d] = 0.f;

    auto stage = [&](int i) {
        const int kt = i * 32;
        const uint32_t base = sb + (uint32_t)(i % 3) * QSTG;
        const int row = tid >> 2, ch = tid & 3;
#pragma unroll
        for (int w = 0; w < 3; w++) {
            const __half* src =
                Wh + (size_t)w * CC * CC + (size_t)(m0 + row) * CC + kt + ch * 8;
            CP_ASYNC(base + (uint32_t)(w * ASTG + row * (APITCH * 2) + ch * 16),
                     src, 16);
        }
#pragma unroll
        for (int t = 0; t < 2; t++) {
            const int idx = t * 256 + tid;
            const int k = idx >> 4, nc = idx & 15;
            const __half* src = X + (size_t)(kt + k) * SPATIAL + n0 + nc * 8;
            CP_ASYNC(base + (uint32_t)(QA + k * 272 + nc * 16), src, 16);
        }
        CP_COMMIT();
    };

    stage(0);
    stage(1);

    for (int i = 0; i < 10; i++) {
        if (i < 8) asm volatile("cp.async.wait_group 1;" ::: "memory");
        else       asm volatile("cp.async.wait_group 0;" ::: "memory");
        __syncthreads();           // single barrier per iter (trailing one removed:
        if (i + 2 < 10) stage(i + 2);  // stage writes (i+2)%3, never read this iter)

        const uint32_t base = sb + (uint32_t)(i % 3) * QSTG;
        const uint32_t bs = base + (uint32_t)QA;

#pragma unroll
        for (int ks = 0; ks < 2; ks++) {
            uint32_t bf[2][4];
#pragma unroll
            for (int nb = 0; nb < 2; nb++) {
                const uint32_t addr = bs +
                    (uint32_t)((ks * 16 + (lane & 15)) * 272 +
                               (wn + nb * 16 + (lane >> 4) * 8) * 2);
                ldsm4t(bf[nb], addr);
            }
#pragma unroll
            for (int w = 0; w < 3; w++) {
                uint32_t af[2][4];
#pragma unroll
                for (int mt = 0; mt < 2; mt++) {
                    const uint32_t addr = base + (uint32_t)(w * ASTG +
                        (wm + mt * 16 + (lane & 15)) * (APITCH * 2) +
                        (lane >> 4) * 16 + ks * 32);
                    ldsm4(af[mt], addr);
                }
#pragma unroll
                for (int nt = 0; nt < 4; nt++) {
                    const uint32_t b0 = bf[nt >> 1][(nt & 1) * 2];
                    const uint32_t b1 = bf[nt >> 1][(nt & 1) * 2 + 1];
                    mma16(c[w][0][nt], af[0], b0, b1);
                    mma16(c[w][1][nt], af[1], b0, b1);
                }
            }
        }
    }

#pragma unroll
    for (int w = 0; w < 3; w++) {
        __half* C = out + (size_t)w * NELEM + (size_t)slab * SLAB;
#pragma unroll
        for (int mt = 0; mt < 2; mt++) {
#pragma unroll
            for (int nt = 0; nt < 4; nt++) {
                const int r0 = m0 + wm + mt * 16 + (lane >> 2);
                const int col = n0 + wn + nt * 8 + (lane & 3) * 2;
                const size_t o0 = (size_t)r0 * SPATIAL + col;
                *(__half2*)(C + o0) =
                    __floats2half2_rn(c[w][mt][nt][0], c[w][mt][nt][1]);
                *(__half2*)(C + o0 + 8ull * SPATIAL) =
                    __floats2half2_rn(c[w][mt][nt][2], c[w][mt][nt][3]);
            }
        }
    }
}

// ================= O projection (BN=256, fp16 residual) =================
#define STG_O (64 * APITCH * 2 + 32 * (256 + 8) * 2)   // 22016

__global__ __launch_bounds__(256, 2) void o_tc(
    const __half* __restrict__ Wh, const __half* __restrict__ O,
    const float* __restrict__ bo, const __half* __restrict__ Rh,
    float* __restrict__ out)
{
    constexpr int BN = 256, BP = BN + 8;
    extern __shared__ char smem[];
    const int slab = blockIdx.z;
    const int m0 = blockIdx.y * 64;
    const int n0 = blockIdx.x * BN;
    const __half* X = O + (size_t)slab * SLAB;
    const __half* R = Rh + (size_t)slab * SLAB;
    float* C = out + (size_t)slab * SLAB;
    const __half* W = Wh + 3ull * CC * CC;

    const int tid = threadIdx.x;
    const int lane = tid & 31, wid = tid >> 5;
    const int wm = (wid & 1) * 32, wn = (wid >> 1) * (BN / 4);
    const uint32_t sb = smem_u32(smem);
    constexpr int ASZ = 64 * APITCH * 2;
    constexpr int STG = ASZ + 32 * BP * 2;

    float c[2][8][4];
#pragma unroll
    for (int a = 0; a < 2; a++)
#pragma unroll
        for (int b = 0; b < 8; b++)
#pragma unroll
            for (int d = 0; d < 4; d++) c[a][b][d] = 0.f;

    auto stage = [&](int i) {
        const int kt = i * 32;
        const uint32_t as = sb + (uint32_t)(i % 3) * STG;
        const uint32_t bs = as + (uint32_t)ASZ;
        {
            const int row = tid >> 2, ch = tid & 3;
            const __half* src = W + (size_t)(m0 + row) * CC + kt + ch * 8;
            CP_ASYNC(as + (uint32_t)(row * (APITCH * 2) + ch * 16), src, 16);
        }
#pragma unroll
        for (int t = 0; t < 4; t++) {
            const int idx = t * 256 + tid;
            const int k = idx >> 5, nc = idx & 31;
            const __half* src = X + (size_t)(kt + k) * SPATIAL + n0 + nc * 8;
            CP_ASYNC(bs + (uint32_t)(k * (BP * 2) + nc * 16), src, 16);
        }
        CP_COMMIT();
    };

    stage(0);
    stage(1);

    for (int i = 0; i < 10; i++) {
        if (i < 8) asm volatile("cp.async.wait_group 1;" ::: "memory");
        else       asm volatile("cp.async.wait_group 0;" ::: "memory");
        __syncthreads();           // single barrier per iter
        if (i + 2 < 10) stage(i + 2);

        const uint32_t as = sb + (uint32_t)(i % 3) * STG;
        const uint32_t bs = as + (uint32_t)ASZ;

#pragma unroll
        for (int ks = 0; ks < 2; ks++) {
            uint32_t af[2][4], bf[4][4];
#pragma unroll
            for (int mt = 0; mt < 2; mt++) {
                const uint32_t addr = as +
                    (uint32_t)((wm + mt * 16 + (lane & 15)) * (APITCH * 2) +
                               (lane >> 4) * 16 + ks * 32);
                ldsm4(af[mt], addr);
            }
#pragma unroll
            for (int nb = 0; nb < 4; nb++) {
                const uint32_t addr = bs +
                    (uint32_t)((ks * 16 + (lane & 15)) * (BP * 2) +
                               (wn + nb * 16 + (lane >> 4) * 8) * 2);
                ldsm4t(bf[nb], addr);
            }
#pragma unroll
            for (int nt = 0; nt < 8; nt++) {
                const uint32_t b0 = bf[nt >> 1][(nt & 1) * 2];
                const uint32_t b1 = bf[nt >> 1][(nt & 1) * 2 + 1];
                mma16(c[0][nt], af[0], b0, b1);
                mma16(c[1][nt], af[1], b0, b1);
            }
        }
    }

#pragma unroll
    for (int mt = 0; mt < 2; mt++) {
#pragma unroll
        for (int nt = 0; nt < 8; nt++) {
            const int r0 = m0 + wm + mt * 16 + (lane >> 2);
            const int col = n0 + wn + nt * 8 + (lane & 3) * 2;
            const size_t o0 = (size_t)r0 * SPATIAL + col;
            const size_t o1 = o0 + 8ull * SPATIAL;
            const float b0v = bo[r0], b1v = bo[r0 + 8];
            const float2 x0 = __half22float2(*(const __half2*)(R + o0));
            const float2 x1 = __half22float2(*(const __half2*)(R + o1));
            *(float2*)(C + o0) = make_float2(c[mt][nt][0] + b0v + x0.x,
                                             c[mt][nt][1] + b0v + x0.y);
            *(float2*)(C + o1) = make_float2(c[mt][nt][2] + b1v + x1.x,
                                             c[mt][nt][3] + b1v + x1.y);
        }
    }
}

// ================= Attention (r12/r13, known good) =================
#define J4 (DH / 8)   // 5 octet-groups

__global__ __launch_bounds__(256, 2) void attn_kernel(
    const __half* __restrict__ Qg, const __half* __restrict__ Kg,
    const __half* __restrict__ Vg, __half* __restrict__ Og,
    const float* __restrict__ relk, const float* __restrict__ relv)
{
    extern __shared__ char smc[];
    uint4* Kp = (uint4*)smc;
    uint4* Vp = Kp + TT * J4 * 32;
    uint4* Rkp = Vp + TT * J4 * 32;
    uint4* Rvp = Rkp + 33 * J4;

    const int b = blockIdx.z;
    const int h = blockIdx.y;
    const int s0 = blockIdx.x * 32;
    const int tid = threadIdx.x;

    __half* Ksh = (__half*)Kp;
    __half* Vsh = (__half*)Vp;
    for (int i = tid; i < TT * DH * 4; i += 256) {
        const int row = i >> 2;
        const int ch = (i & 3) * 8;
        const int f = row / DH, dd = row - f * DH;
        const size_t g =
            ((size_t)((b * TT + f) * CC + h * DH + dd)) * SPATIAL + s0 + ch;
        uint4 kk = *(const uint4*)(Kg + g);
        uint4 vv = *(const uint4*)(Vg + g);
        __half kh[8], vh[8];
        *(uint4*)kh = kk;
        *(uint4*)vh = vv;
        const int wb = (f * J4 + (dd >> 3)) * 32;
        const int e0 = dd & 7;
#pragma unroll
        for (int e = 0; e < 8; e++) {
            const int w = (wb + ch + e) * 8 + e0;
            Ksh[w] = kh[e];
            Vsh[w] = vh[e];
        }
    }
    __half* Rkh = (__half*)Rkp;
    __half* Rvh = (__half*)Rvp;
    for (int i = tid; i < 33 * DH; i += 256) {
        Rkh[i] = __float2half_rn(relk[i]);
        Rvh[i] = __float2half_rn(relv[i]);
    }
    __syncthreads();

    const int sl = tid & 31;
    const int tg = tid >> 5;
    const float scale = 0.15811388300841898f;  // 40^-0.5

    for (int rep = 0; rep < 2; rep++) {
        const int t = rep ? (15 - tg) : tg;    // warp-uniform
        const size_t base =
            ((size_t)((b * TT + t) * CC + h * DH)) * SPATIAL + s0 + sl;

        float qo[DH];
#pragma unroll
        for (int dd = 0; dd < DH; dd++)
            qo[dd] = __half2float(Qg[base + (size_t)dd * SPATIAL]) * scale;

        float sim[TT];
        float mx = -1e30f;
#pragma unroll
        for (int sp = 0; sp < TT; sp++) {
            if (sp > t) break;
            const uint4* kp = Kp + (sp * J4) * 32 + sl;
            const uint4* rp = Rkp + (sp - t + TT) * J4;
            float p0 = 0.f, p1 = 0.f, p2 = 0.f, p3 = 0.f;
#pragma unroll
            for (int j = 0; j < J4; j++) {
                const uint4 kv = kp[j * 32];
                const uint4 rv = rp[j];
                const float2 f0 = __half22float2(__hadd2(u2h2(kv.x), u2h2(rv.x)));
                const float2 f1 = __half22float2(__hadd2(u2h2(kv.y), u2h2(rv.y)));
                const float2 f2 = __half22float2(__hadd2(u2h2(kv.z), u2h2(rv.z)));
                const float2 f3 = __half22float2(__hadd2(u2h2(kv.w), u2h2(rv.w)));
                p0 = fmaf(qo[8 * j],     f0.x, p0);
                p1 = fmaf(qo[8 * j + 1], f0.y, p1);
                p2 = fmaf(qo[8 * j + 2], f1.x, p2);
                p3 = fmaf(qo[8 * j + 3], f1.y, p3);
                p0 = fmaf(qo[8 * j + 4], f2.x, p0);
                p1 = fmaf(qo[8 * j + 5], f2.y, p1);
                p2 = fmaf(qo[8 * j + 6], f3.x, p2);
                p3 = fmaf(qo[8 * j + 7], f3.y, p3);
            }
            const float acc = (p0 + p1) + (p2 + p3);
            sim[sp] = acc;
            mx = fmaxf(mx, acc);
        }
        float den = 0.f;
#pragma unroll
        for (int sp = 0; sp < TT; sp++) {
            if (sp > t) break;
            const float e = __expf(sim[sp] - mx);
            sim[sp] = e;
            den += e;
        }
        const float inv = 1.f / den;

#pragma unroll
        for (int dd = 0; dd < DH; dd++) qo[dd] = 0.f;
#pragma unroll
        for (int sp = 0; sp < TT; sp++) {
            if (sp > t) break;
            const float a = sim[sp] * inv;
            const uint4* vp = Vp + (sp * J4) * 32 + sl;
            const uint4* rp = Rvp + (sp - t + TT) * J4;
#pragma unroll
            for (int j = 0; j < J4; j++) {
                const uint4 vv = vp[j * 32];
                const uint4 rv = rp[j];
                const float2 f0 = __half22float2(__hadd2(u2h2(vv.x), u2h2(rv.x)));
                const float2 f1 = __half22float2(__hadd2(u2h2(vv.y), u2h2(rv.y)));
                const float2 f2 = __half22float2(__hadd2(u2h2(vv.z), u2h2(rv.z)));
                const float2 f3 = __half22float2(__hadd2(u2h2(vv.w), u2h2(rv.w)));
                qo[8 * j]     = fmaf(a, f0.x, qo[8 * j]);
                qo[8 * j + 1] = fmaf(a, f0.y, qo[8 * j + 1]);
                qo[8 * j + 2] = fmaf(a, f1.x, qo[8 * j + 2]);
                qo[8 * j + 3] = fmaf(a, f1.y, qo[8 * j + 3]);
                qo[8 * j + 4] = fmaf(a, f2.x, qo[8 * j + 4]);
                qo[8 * j + 5] = fmaf(a, f2.y, qo[8 * j + 5]);
                qo[8 * j + 6] = fmaf(a, f3.x, qo[8 * j + 6]);
                qo[8 * j + 7] = fmaf(a, f3.y, qo[8 * j + 7]);
            }
        }
#pragma unroll
        for (int dd = 0; dd < DH; dd++)
            Og[base + (size_t)dd * SPATIAL] = __float2half_rn(qo[dd]);
    }
}

// ================= launch (serial single-stream, proven) =================
extern "C" void kernel_launch(void* const* d_in, const int* in_sizes, int n_in,
                              void* d_out, int out_size) {
    const float* x  = (const float*)d_in[0];
    const float* Wq = (const float*)d_in[1];
    const float* Wk = (const float*)d_in[2];
    const float* Wv = (const float*)d_in[3];
    const float* Wo = (const float*)d_in[4];
    const float* bo = (const float*)d_in[5];
    const float* rk = (const float*)d_in[6];
    const float* rv = (const float*)d_in[7];
    float* out = (float*)d_out;

    __half* hb = nullptr;
    cudaGetSymbolAddress((void**)&hb, g_hbuf);
    __half* Q  = hb;
    __half* K  = hb + 1ull * NELEM;
    __half* V  = hb + 2ull * NELEM;
    __half* O  = hb + 3ull * NELEM;
    __half* Xh = hb + 4ull * NELEM;
    __half* Wh = hb + 5ull * NELEM;

    cvt_all<<<XB + WB, 256>>>(x, Wq, Wk, Wv, Wo, Xh, Wh);

    cudaFuncSetAttribute((const void*)qkv_tc,
                         cudaFuncAttributeMaxDynamicSharedMemorySize, 3 * QSTG);
    cudaFuncSetAttribute((const void*)o_tc,
                         cudaFuncAttributeMaxDynamicSharedMemorySize, 3 * STG_O);

    qkv_tc<<<dim3(SPATIAL / 128, CC / 64, NSLAB), 256, 3 * QSTG>>>(Wh, Xh, hb);

    const int asmb = 87200;
    cudaFuncSetAttribute((const void*)attn_kernel,
                         cudaFuncAttributeMaxDynamicSharedMemorySize, asmb);
    attn_kernel<<<dim3(SPATIAL / 32, HEADS, 4), 256, asmb>>>(Q, K, V, O, rk, rv);

    o_tc<<<dim3(SPATIAL / 256, CC / 64, NSLAB), 256, 3 * STG_O>>>(Wh, O, bo, Xh, out);
}

// round 16
// speedup vs baseline: 1.2326x; 1.0099x over previous
#include <cuda_runtime.h>
#include <cuda_fp16.h>
#include <cstdint>
#include <cstddef>

#define TT 16
#define HEADS 8
#define DH 40
#define CC 320
#define SPATIAL 1024
#define NSLAB 64
#define SLAB (CC * SPATIAL)
#define NELEM (1ull * NSLAB * SLAB)   // 20,971,520

// fp16 scratch: Q,K,V,O, Xh (5 x NELEM) + 4 converted W matrices
__device__ __half g_hbuf[5ull * NELEM + 4ull * CC * CC];

// ================= helpers =================
__device__ __forceinline__ uint32_t smem_u32(const void* p) {
    uint32_t a;
    asm("{ .reg .u64 t; cvta.to.shared.u64 t, %1; cvt.u32.u64 %0, t; }"
        : "=r"(a) : "l"(p));
    return a;
}
__device__ __forceinline__ void ldsm4(uint32_t* r, uint32_t a) {
    asm volatile("ldmatrix.sync.aligned.m8n8.x4.shared.b16 {%0,%1,%2,%3}, [%4];"
                 : "=r"(r[0]), "=r"(r[1]), "=r"(r[2]), "=r"(r[3]) : "r"(a));
}
__device__ __forceinline__ void ldsm4t(uint32_t* r, uint32_t a) {
    asm volatile("ldmatrix.sync.aligned.m8n8.x4.trans.shared.b16 {%0,%1,%2,%3}, [%4];"
                 : "=r"(r[0]), "=r"(r[1]), "=r"(r[2]), "=r"(r[3]) : "r"(a));
}
__device__ __forceinline__ void mma16(float* c, const uint32_t* a,
                                      uint32_t b0, uint32_t b1) {
    asm volatile(
        "mma.sync.aligned.m16n8k16.row.col.f32.f16.f16.f32 "
        "{%0,%1,%2,%3},{%4,%5,%6,%7},{%8,%9},{%0,%1,%2,%3};"
        : "+f"(c[0]), "+f"(c[1]), "+f"(c[2]), "+f"(c[3])
        : "r"(a[0]), "r"(a[1]), "r"(a[2]), "r"(a[3]), "r"(b0), "r"(b1));
}
#define CP_ASYNC(dst, src, sz) \
    asm volatile("cp.async.cg.shared.global [%0], [%1], 16, %2;" \
                 :: "r"(dst), "l"(src), "r"(sz))
#define CP_COMMIT() asm volatile("cp.async.commit_group;" ::: "memory")

__device__ __forceinline__ __half2 u2h2(uint32_t u) {
    __half2 h; *(uint32_t*)&h = u; return h;
}

// ================= fused conversion kernel =================
#define XB ((unsigned)(NELEM / 2048))        // 10240
#define WB ((unsigned)(4 * CC * CC / 2048))  // 200

__global__ __launch_bounds__(256) void cvt_all(
    const float* __restrict__ x,
    const float* __restrict__ Wq, const float* __restrict__ Wk,
    const float* __restrict__ Wv, const float* __restrict__ Wo,
    __half* __restrict__ xh, __half* __restrict__ wh)
{
    const unsigned bx = blockIdx.x;
    const float* src;
    __half* dst;
    size_t i;
    if (bx < XB) {
        i = ((size_t)bx * 256 + threadIdx.x) * 8;
        src = x; dst = xh;
    } else {
        i = ((size_t)(bx - XB) * 256 + threadIdx.x) * 8;   // < 409600
        const size_t wsz = (size_t)CC * CC;
        const int z = (int)(i / wsz);
        src = (z == 0) ? Wq : (z == 1) ? Wk : (z == 2) ? Wv : Wo;
        src -= z * wsz;
        dst = wh;
    }
    float4 a = *(const float4*)(src + i);
    float4 b = *(const float4*)(src + i + 4);
    __half2 h[4] = { __floats2half2_rn(a.x, a.y), __floats2half2_rn(a.z, a.w),
                     __floats2half2_rn(b.x, b.y), __floats2half2_rn(b.z, b.w) };
    *(uint4*)(dst + i) = *(uint4*)h;
}

// ================= fused QKV GEMM (BK=64, 2-stage) =================
// One CTA computes Q,K,V 64x128 tiles; B loaded once, reused across 3 W.
// 8 warps (2m x 4n), warp tile 32x32. K=320 = 5 iters of BK=64.
#define AP2 72                       // A pitch (halves) for 64-half rows
#define ASTG2 (64 * AP2 * 2)         // 9216 B per W
#define QA2 (3 * ASTG2)              // 27648
#define QSTG2 (QA2 + 64 * 136 * 2)   // 45056

__global__ __launch_bounds__(256, 2) void qkv_tc(
    const __half* __restrict__ Wh, const __half* __restrict__ Xh,
    __half* __restrict__ out)
{
    extern __shared__ char smem[];
    const int slab = blockIdx.z;
    const int m0 = blockIdx.y * 64;
    const int n0 = blockIdx.x * 128;
    const __half* X = Xh + (size_t)slab * SLAB;

    const int tid = threadIdx.x;
    const int lane = tid & 31, wid = tid >> 5;
    const int wm = (wid & 1) * 32, wn = (wid >> 1) * 32;
    const uint32_t sb = smem_u32(smem);

    float c[3][2][4][4];
#pragma unroll
    for (int w = 0; w < 3; w++)
#pragma unroll
        for (int a = 0; a < 2; a++)
#pragma unroll
            for (int b = 0; b < 4; b++)
#pragma unroll
                for (int d = 0; d < 4; d++) c[w][a][b][d] = 0.f;

    auto stage = [&](int i) {
        const int kt = i * 64;
        const uint32_t base = sb + (uint32_t)(i & 1) * QSTG2;
        // A: per W, 64 rows x 64 halves = 512 x 16B chunks (2/thread)
#pragma unroll
        for (int t = 0; t < 2; t++) {
            const int idx = t * 256 + tid;
            const int row = idx >> 3, ch = idx & 7;
#pragma unroll
            for (int w = 0; w < 3; w++) {
                const __half* src =
                    Wh + (size_t)w * CC * CC + (size_t)(m0 + row) * CC + kt + ch * 8;
                CP_ASYNC(base + (uint32_t)(w * ASTG2 + row * (AP2 * 2) + ch * 16),
                         src, 16);
            }
        }
        // B: 64 k-rows x 128 halves = 1024 x 16B chunks (4/thread)
#pragma unroll
        for (int t = 0; t < 4; t++) {
            const int idx = t * 256 + tid;
            const int k = idx >> 4, nc = idx & 15;
            const __half* src = X + (size_t)(kt + k) * SPATIAL + n0 + nc * 8;
            CP_ASYNC(base + (uint32_t)(QA2 + k * 272 + nc * 16), src, 16);
        }
        CP_COMMIT();
    };

    stage(0);
    stage(1);

    for (int i = 0; i < 5; i++) {
        if (i < 4) asm volatile("cp.async.wait_group 1;" ::: "memory");
        else       asm volatile("cp.async.wait_group 0;" ::: "memory");
        __syncthreads();

        const uint32_t base = sb + (uint32_t)(i & 1) * QSTG2;
        const uint32_t bs = base + (uint32_t)QA2;

#pragma unroll
        for (int ks = 0; ks < 4; ks++) {
            uint32_t bf[2][4];
#pragma unroll
            for (int nb = 0; nb < 2; nb++) {
                const uint32_t addr = bs +
                    (uint32_t)((ks * 16 + (lane & 15)) * 272 +
                               (wn + nb * 16 + (lane >> 4) * 8) * 2);
                ldsm4t(bf[nb], addr);
            }
#pragma unroll
            for (int w = 0; w < 3; w++) {
                uint32_t af[2][4];
#pragma unroll
                for (int mt = 0; mt < 2; mt++) {
                    const uint32_t addr = base + (uint32_t)(w * ASTG2 +
                        (wm + mt * 16 + (lane & 15)) * (AP2 * 2) +
                        (lane >> 4) * 16 + ks * 32);
                    ldsm4(af[mt], addr);
                }
#pragma unroll
                for (int nt = 0; nt < 4; nt++) {
                    const uint32_t b0 = bf[nt >> 1][(nt & 1) * 2];
                    const uint32_t b1 = bf[nt >> 1][(nt & 1) * 2 + 1];
                    mma16(c[w][0][nt], af[0], b0, b1);
                    mma16(c[w][1][nt], af[1], b0, b1);
                }
            }
        }
        __syncthreads();               // buffer i&1 fully consumed
        if (i + 2 < 5) stage(i + 2);   // safe: writes buffer i&1 after barrier
    }

#pragma unroll
    for (int w = 0; w < 3; w++) {
        __half* C = out + (size_t)w * NELEM + (size_t)slab * SLAB;
#pragma unroll
        for (int mt = 0; mt < 2; mt++) {
#pragma unroll
            for (int nt = 0; nt < 4; nt++) {
                const int r0 = m0 + wm + mt * 16 + (lane >> 2);
                const int col = n0 + wn + nt * 8 + (lane & 3) * 2;
                const size_t o0 = (size_t)r0 * SPATIAL + col;
                *(__half2*)(C + o0) =
                    __floats2half2_rn(c[w][mt][nt][0], c[w][mt][nt][1]);
                *(__half2*)(C + o0 + 8ull * SPATIAL) =
                    __floats2half2_rn(c[w][mt][nt][2], c[w][mt][nt][3]);
            }
        }
    }
}

// ================= O projection (BN=256, BK=64, 2-stage, fp16 residual) ======
#define OASZ ASTG2                       // 9216
#define OSTG (OASZ + 64 * 264 * 2)       // 43008

__global__ __launch_bounds__(256, 2) void o_tc(
    const __half* __restrict__ Wh, const __half* __restrict__ O,
    const float* __restrict__ bo, const __half* __restrict__ Rh,
    float* __restrict__ out)
{
    constexpr int BN = 256, BP = BN + 8;
    extern __shared__ char smem[];
    const int slab = blockIdx.z;
    const int m0 = blockIdx.y * 64;
    const int n0 = blockIdx.x * BN;
    const __half* X = O + (size_t)slab * SLAB;
    const __half* R = Rh + (size_t)slab * SLAB;
    float* C = out + (size_t)slab * SLAB;
    const __half* W = Wh + 3ull * CC * CC;

    const int tid = threadIdx.x;
    const int lane = tid & 31, wid = tid >> 5;
    const int wm = (wid & 1) * 32, wn = (wid >> 1) * (BN / 4);
    const uint32_t sb = smem_u32(smem);

    float c[2][8][4];
#pragma unroll
    for (int a = 0; a < 2; a++)
#pragma unroll
        for (int b = 0; b < 8; b++)
#pragma unroll
            for (int d = 0; d < 4; d++) c[a][b][d] = 0.f;

    auto stage = [&](int i) {
        const int kt = i * 64;
        const uint32_t as = sb + (uint32_t)(i & 1) * OSTG;
        const uint32_t bs = as + (uint32_t)OASZ;
        // A: 64 rows x 64 halves = 512 chunks (2/thread)
#pragma unroll
        for (int t = 0; t < 2; t++) {
            const int idx = t * 256 + tid;
            const int row = idx >> 3, ch = idx & 7;
            const __half* src = W + (size_t)(m0 + row) * CC + kt + ch * 8;
            CP_ASYNC(as + (uint32_t)(row * (AP2 * 2) + ch * 16), src, 16);
        }
        // B: 64 k-rows x 256 halves = 2048 chunks (8/thread)
#pragma unroll
        for (int t = 0; t < 8; t++) {
            const int idx = t * 256 + tid;
            const int k = idx >> 5, nc = idx & 31;
            const __half* src = X + (size_t)(kt + k) * SPATIAL + n0 + nc * 8;
            CP_ASYNC(bs + (uint32_t)(k * (BP * 2) + nc * 16), src, 16);
        }
        CP_COMMIT();
    };

    stage(0);
    stage(1);

    for (int i = 0; i < 5; i++) {
        if (i < 4) asm volatile("cp.async.wait_group 1;" ::: "memory");
        else       asm volatile("cp.async.wait_group 0;" ::: "memory");
        __syncthreads();

        const uint32_t as = sb + (uint32_t)(i & 1) * OSTG;
        const uint32_t bs = as + (uint32_t)OASZ;

#pragma unroll
        for (int ks = 0; ks < 4; ks++) {
            uint32_t af[2][4], bf[4][4];
#pragma unroll
            for (int mt = 0; mt < 2; mt++) {
                const uint32_t addr = as +
                    (uint32_t)((wm + mt * 16 + (lane & 15)) * (AP2 * 2) +
                               (lane >> 4) * 16 + ks * 32);
                ldsm4(af[mt], addr);
            }
#pragma unroll
            for (int nb = 0; nb < 4; nb++) {
                const uint32_t addr = bs +
                    (uint32_t)((ks * 16 + (lane & 15)) * (BP * 2) +
                               (wn + nb * 16 + (lane >> 4) * 8) * 2);
                ldsm4t(bf[nb], addr);
            }
#pragma unroll
            for (int nt = 0; nt < 8; nt++) {
                const uint32_t b0 = bf[nt >> 1][(nt & 1) * 2];
                const uint32_t b1 = bf[nt >> 1][(nt & 1) * 2 + 1];
                mma16(c[0][nt], af[0], b0, b1);
                mma16(c[1][nt], af[1], b0, b1);
            }
        }
        __syncthreads();
        if (i + 2 < 5) stage(i + 2);
    }

#pragma unroll
    for (int mt = 0; mt < 2; mt++) {
#pragma unroll
        for (int nt = 0; nt < 8; nt++) {
            const int r0 = m0 + wm + mt * 16 + (lane >> 2);
            const int col = n0 + wn + nt * 8 + (lane & 3) * 2;
            const size_t o0 = (size_t)r0 * SPATIAL + col;
            const size_t o1 = o0 + 8ull * SPATIAL;
            const float b0v = bo[r0], b1v = bo[r0 + 8];
            const float2 x0 = __half22float2(*(const __half2*)(R + o0));
            const float2 x1 = __half22float2(*(const __half2*)(R + o1));
            *(float2*)(C + o0) = make_float2(c[mt][nt][0] + b0v + x0.x,
                                             c[mt][nt][1] + b0v + x0.y);
            *(float2*)(C + o1) = make_float2(c[mt][nt][2] + b1v + x1.x,
                                             c[mt][nt][3] + b1v + x1.y);
        }
    }
}

// ================= Attention (r12/r13/r15, known good) =================
#define J4 (DH / 8)   // 5 octet-groups

__global__ __launch_bounds__(256, 2) void attn_kernel(
    const __half* __restrict__ Qg, const __half* __restrict__ Kg,
    const __half* __restrict__ Vg, __half* __restrict__ Og,
    const float* __restrict__ relk, const float* __restrict__ relv)
{
    extern __shared__ char smc[];
    uint4* Kp = (uint4*)smc;
    uint4* Vp = Kp + TT * J4 * 32;
    uint4* Rkp = Vp + TT * J4 * 32;
    uint4* Rvp = Rkp + 33 * J4;

    const int b = blockIdx.z;
    const int h = blockIdx.y;
    const int s0 = blockIdx.x * 32;
    const int tid = threadIdx.x;

    __half* Ksh = (__half*)Kp;
    __half* Vsh = (__half*)Vp;
    for (int i = tid; i < TT * DH * 4; i += 256) {
        const int row = i >> 2;
        const int ch = (i & 3) * 8;
        const int f = row / DH, dd = row - f * DH;
        const size_t g =
            ((size_t)((b * TT + f) * CC + h * DH + dd)) * SPATIAL + s0 + ch;
        uint4 kk = *(const uint4*)(Kg + g);
        uint4 vv = *(const uint4*)(Vg + g);
        __half kh[8], vh[8];
        *(uint4*)kh = kk;
        *(uint4*)vh = vv;
        const int wb = (f * J4 + (dd >> 3)) * 32;
        const int e0 = dd & 7;
#pragma unroll
        for (int e = 0; e < 8; e++) {
            const int w = (wb + ch + e) * 8 + e0;
            Ksh[w] = kh[e];
            Vsh[w] = vh[e];
        }
    }
    __half* Rkh = (__half*)Rkp;
    __half* Rvh = (__half*)Rvp;
    for (int i = tid; i < 33 * DH; i += 256) {
        Rkh[i] = __float2half_rn(relk[i]);
        Rvh[i] = __float2half_rn(relv[i]);
    }
    __syncthreads();

    const int sl = tid & 31;
    const int tg = tid >> 5;
    const float scale = 0.15811388300841898f;  // 40^-0.5

    for (int rep = 0; rep < 2; rep++) {
        const int t = rep ? (15 - tg) : tg;    // warp-uniform
        const size_t base =
            ((size_t)((b * TT + t) * CC + h * DH)) * SPATIAL + s0 + sl;

        float qo[DH];
#pragma unroll
        for (int dd = 0; dd < DH; dd++)
            qo[dd] = __half2float(Qg[base + (size_t)dd * SPATIAL]) * scale;

        float sim[TT];
        float mx = -1e30f;
#pragma unroll
        for (int sp = 0; sp < TT; sp++) {
            if (sp > t) break;
            const uint4* kp = Kp + (sp * J4) * 32 + sl;
            const uint4* rp = Rkp + (sp - t + TT) * J4;
            float p0 = 0.f, p1 = 0.f, p2 = 0.f, p3 = 0.f;
#pragma unroll
            for (int j = 0; j < J4; j++) {
                const uint4 kv = kp[j * 32];
                const uint4 rv = rp[j];
                const float2 f0 = __half22float2(__hadd2(u2h2(kv.x), u2h2(rv.x)));
                const float2 f1 = __half22float2(__hadd2(u2h2(kv.y), u2h2(rv.y)));
                const float2 f2 = __half22float2(__hadd2(u2h2(kv.z), u2h2(rv.z)));
                const float2 f3 = __half22float2(__hadd2(u2h2(kv.w), u2h2(rv.w)));
                p0 = fmaf(qo[8 * j],     f0.x, p0);
                p1 = fmaf(qo[8 * j + 1], f0.y, p1);
                p2 = fmaf(qo[8 * j + 2], f1.x, p2);
                p3 = fmaf(qo[8 * j + 3], f1.y, p3);
                p0 = fmaf(qo[8 * j + 4], f2.x, p0);
                p1 = fmaf(qo[8 * j + 5], f2.y, p1);
                p2 = fmaf(qo[8 * j + 6], f3.x, p2);
                p3 = fmaf(qo[8 * j + 7], f3.y, p3);
            }
            const float acc = (p0 + p1) + (p2 + p3);
            sim[sp] = acc;
            mx = fmaxf(mx, acc);
        }
        float den = 0.f;
#pragma unroll
        for (int sp = 0; sp < TT; sp++) {
            if (sp > t) break;
            const float e = __expf(sim[sp] - mx);
            sim[sp] = e;
            den += e;
        }
        const float inv = 1.f / den;

#pragma unroll
        for (int dd = 0; dd < DH; dd++) qo[dd] = 0.f;
#pragma unroll
        for (int sp = 0; sp < TT; sp++) {
            if (sp > t) break;
            const float a = sim[sp] * inv;
            const uint4* vp = Vp + (sp * J4) * 32 + sl;
            const uint4* rp = Rvp + (sp - t + TT) * J4;
#pragma unroll
            for (int j = 0; j < J4; j++) {
                const uint4 vv = vp[j * 32];
                const uint4 rv = rp[j];
                const float2 f0 = __half22float2(__hadd2(u2h2(vv.x), u2h2(rv.x)));
                const float2 f1 = __half22float2(__hadd2(u2h2(vv.y), u2h2(rv.y)));
                const float2 f2 = __half22float2(__hadd2(u2h2(vv.z), u2h2(rv.z)));
                const float2 f3 = __half22float2(__hadd2(u2h2(vv.w), u2h2(rv.w)));
                qo[8 * j]     = fmaf(a, f0.x, qo[8 * j]);
                qo[8 * j + 1] = fmaf(a, f0.y, qo[8 * j + 1]);
                qo[8 * j + 2] = fmaf(a, f1.x, qo[8 * j + 2]);
                qo[8 * j + 3] = fmaf(a, f1.y, qo[8 * j + 3]);
                qo[8 * j + 4] = fmaf(a, f2.x, qo[8 * j + 4]);
                qo[8 * j + 5] = fmaf(a, f2.y, qo[8 * j + 5]);
                qo[8 * j + 6] = fmaf(a, f3.x, qo[8 * j + 6]);
                qo[8 * j + 7] = fmaf(a, f3.y, qo[8 * j + 7]);
            }
        }
#pragma unroll
        for (int dd = 0; dd < DH; dd++)
            Og[base + (size_t)dd * SPATIAL] = __float2half_rn(qo[dd]);
    }
}

// ================= launch =================
extern "C" void kernel_launch(void* const* d_in, const int* in_sizes, int n_in,
                              void* d_out, int out_size) {
    const float* x  = (const float*)d_in[0];
    const float* Wq = (const float*)d_in[1];
    const float* Wk = (const float*)d_in[2];
    const float* Wv = (const float*)d_in[3];
    const float* Wo = (const float*)d_in[4];
    const float* bo = (const float*)d_in[5];
    const float* rk = (const float*)d_in[6];
    const float* rv = (const float*)d_in[7];
    float* out = (float*)d_out;

    __half* hb = nullptr;
    cudaGetSymbolAddress((void**)&hb, g_hbuf);
    __half* Q  = hb;
    __half* K  = hb + 1ull * NELEM;
    __half* V  = hb + 2ull * NELEM;
    __half* O  = hb + 3ull * NELEM;
    __half* Xh = hb + 4ull * NELEM;
    __half* Wh = hb + 5ull * NELEM;

    cvt_all<<<XB + WB, 256>>>(x, Wq, Wk, Wv, Wo, Xh, Wh);

    cudaFuncSetAttribute((const void*)qkv_tc,
                         cudaFuncAttributeMaxDynamicSharedMemorySize, 2 * QSTG2);
    cudaFuncSetAttribute((const void*)o_tc,
                         cudaFuncAttributeMaxDynamicSharedMemorySize, 2 * OSTG);

    qkv_tc<<<dim3(SPATIAL / 128, CC / 64, NSLAB), 256, 2 * QSTG2>>>(Wh, Xh, hb);

    const int asmb = 87200;
    cudaFuncSetAttribute((const void*)attn_kernel,
                         cudaFuncAttributeMaxDynamicSharedMemorySize, asmb);
    attn_kernel<<<dim3(SPATIAL / 32, HEADS, 4), 256, asmb>>>(Q, K, V, O, rk, rv);

    o_tc<<<dim3(SPATIAL / 256, CC / 64, NSLAB), 256, 2 * OSTG>>>(Wh, O, bo, Xh, out);
}

// round 17
// speedup vs baseline: 1.2510x; 1.0150x over previous
#include <cuda_runtime.h>
#include <cuda_fp16.h>
#include <cstdint>
#include <cstddef>

#define TT 16
#define HEADS 8
#define DH 40
#define CC 320
#define SPATIAL 1024
#define NSLAB 64
#define SLAB (CC * SPATIAL)
#define NELEM (1ull * NSLAB * SLAB)   // 20,971,520

// fp16 scratch: Q,K,V,O, Xh (5 x NELEM) + 4 converted W matrices
__device__ __half g_hbuf[5ull * NELEM + 4ull * CC * CC];

// ================= helpers =================
__device__ __forceinline__ uint32_t smem_u32(const void* p) {
    uint32_t a;
    asm("{ .reg .u64 t; cvta.to.shared.u64 t, %1; cvt.u32.u64 %0, t; }"
        : "=r"(a) : "l"(p));
    return a;
}
__device__ __forceinline__ void ldsm4(uint32_t* r, uint32_t a) {
    asm volatile("ldmatrix.sync.aligned.m8n8.x4.shared.b16 {%0,%1,%2,%3}, [%4];"
                 : "=r"(r[0]), "=r"(r[1]), "=r"(r[2]), "=r"(r[3]) : "r"(a));
}
__device__ __forceinline__ void ldsm4t(uint32_t* r, uint32_t a) {
    asm volatile("ldmatrix.sync.aligned.m8n8.x4.trans.shared.b16 {%0,%1,%2,%3}, [%4];"
                 : "=r"(r[0]), "=r"(r[1]), "=r"(r[2]), "=r"(r[3]) : "r"(a));
}
__device__ __forceinline__ void mma16(float* c, const uint32_t* a,
                                      uint32_t b0, uint32_t b1) {
    asm volatile(
        "mma.sync.aligned.m16n8k16.row.col.f32.f16.f16.f32 "
        "{%0,%1,%2,%3},{%4,%5,%6,%7},{%8,%9},{%0,%1,%2,%3};"
        : "+f"(c[0]), "+f"(c[1]), "+f"(c[2]), "+f"(c[3])
        : "r"(a[0]), "r"(a[1]), "r"(a[2]), "r"(a[3]), "r"(b0), "r"(b1));
}
#define CP_ASYNC(dst, src, sz) \
    asm volatile("cp.async.cg.shared.global [%0], [%1], 16, %2;" \
                 :: "r"(dst), "l"(src), "r"(sz))
#define CP_COMMIT() asm volatile("cp.async.commit_group;" ::: "memory")

__device__ __forceinline__ __half2 u2h2(uint32_t u) {
    __half2 h; *(uint32_t*)&h = u; return h;
}

// ================= fused conversion kernel =================
#define XB ((unsigned)(NELEM / 2048))        // 10240
#define WB ((unsigned)(4 * CC * CC / 2048))  // 200

__global__ __launch_bounds__(256) void cvt_all(
    const float* __restrict__ x,
    const float* __restrict__ Wq, const float* __restrict__ Wk,
    const float* __restrict__ Wv, const float* __restrict__ Wo,
    __half* __restrict__ xh, __half* __restrict__ wh)
{
    const unsigned bx = blockIdx.x;
    const float* src;
    __half* dst;
    size_t i;
    if (bx < XB) {
        i = ((size_t)bx * 256 + threadIdx.x) * 8;
        src = x; dst = xh;
    } else {
        i = ((size_t)(bx - XB) * 256 + threadIdx.x) * 8;   // < 409600
        const size_t wsz = (size_t)CC * CC;
        const int z = (int)(i / wsz);
        src = (z == 0) ? Wq : (z == 1) ? Wk : (z == 2) ? Wv : Wo;
        src -= z * wsz;
        dst = wh;
    }
    float4 a = *(const float4*)(src + i);
    float4 b = *(const float4*)(src + i + 4);
    __half2 h[4] = { __floats2half2_rn(a.x, a.y), __floats2half2_rn(a.z, a.w),
                     __floats2half2_rn(b.x, b.y), __floats2half2_rn(b.z, b.w) };
    *(uint4*)(dst + i) = *(uint4*)h;
}

// ================= fused QKV GEMM (BK=64, 2-stage — r16 winner) =================
#define AP2 72                       // A pitch (halves) for 64-half rows
#define ASTG2 (64 * AP2 * 2)         // 9216 B per W
#define QA2 (3 * ASTG2)              // 27648
#define QSTG2 (QA2 + 64 * 136 * 2)   // 45056

__global__ __launch_bounds__(256, 2) void qkv_tc(
    const __half* __restrict__ Wh, const __half* __restrict__ Xh,
    __half* __restrict__ out)
{
    extern __shared__ char smem[];
    const int slab = blockIdx.z;
    const int m0 = blockIdx.y * 64;
    const int n0 = blockIdx.x * 128;
    const __half* X = Xh + (size_t)slab * SLAB;

    const int tid = threadIdx.x;
    const int lane = tid & 31, wid = tid >> 5;
    const int wm = (wid & 1) * 32, wn = (wid >> 1) * 32;
    const uint32_t sb = smem_u32(smem);

    float c[3][2][4][4];
#pragma unroll
    for (int w = 0; w < 3; w++)
#pragma unroll
        for (int a = 0; a < 2; a++)
#pragma unroll
            for (int b = 0; b < 4; b++)
#pragma unroll
                for (int d = 0; d < 4; d++) c[w][a][b][d] = 0.f;

    auto stage = [&](int i) {
        const int kt = i * 64;
        const uint32_t base = sb + (uint32_t)(i & 1) * QSTG2;
#pragma unroll
        for (int t = 0; t < 2; t++) {
            const int idx = t * 256 + tid;
            const int row = idx >> 3, ch = idx & 7;
#pragma unroll
            for (int w = 0; w < 3; w++) {
                const __half* src =
                    Wh + (size_t)w * CC * CC + (size_t)(m0 + row) * CC + kt + ch * 8;
                CP_ASYNC(base + (uint32_t)(w * ASTG2 + row * (AP2 * 2) + ch * 16),
                         src, 16);
            }
        }
#pragma unroll
        for (int t = 0; t < 4; t++) {
            const int idx = t * 256 + tid;
            const int k = idx >> 4, nc = idx & 15;
            const __half* src = X + (size_t)(kt + k) * SPATIAL + n0 + nc * 8;
            CP_ASYNC(base + (uint32_t)(QA2 + k * 272 + nc * 16), src, 16);
        }
        CP_COMMIT();
    };

    stage(0);
    stage(1);

    for (int i = 0; i < 5; i++) {
        if (i < 4) asm volatile("cp.async.wait_group 1;" ::: "memory");
        else       asm volatile("cp.async.wait_group 0;" ::: "memory");
        __syncthreads();

        const uint32_t base = sb + (uint32_t)(i & 1) * QSTG2;
        const uint32_t bs = base + (uint32_t)QA2;

#pragma unroll
        for (int ks = 0; ks < 4; ks++) {
            uint32_t bf[2][4];
#pragma unroll
            for (int nb = 0; nb < 2; nb++) {
                const uint32_t addr = bs +
                    (uint32_t)((ks * 16 + (lane & 15)) * 272 +
                               (wn + nb * 16 + (lane >> 4) * 8) * 2);
                ldsm4t(bf[nb], addr);
            }
#pragma unroll
            for (int w = 0; w < 3; w++) {
                uint32_t af[2][4];
#pragma unroll
                for (int mt = 0; mt < 2; mt++) {
                    const uint32_t addr = base + (uint32_t)(w * ASTG2 +
                        (wm + mt * 16 + (lane & 15)) * (AP2 * 2) +
                        (lane >> 4) * 16 + ks * 32);
                    ldsm4(af[mt], addr);
                }
#pragma unroll
                for (int nt = 0; nt < 4; nt++) {
                    const uint32_t b0 = bf[nt >> 1][(nt & 1) * 2];
                    const uint32_t b1 = bf[nt >> 1][(nt & 1) * 2 + 1];
                    mma16(c[w][0][nt], af[0], b0, b1);
                    mma16(c[w][1][nt], af[1], b0, b1);
                }
            }
        }
        __syncthreads();               // buffer i&1 fully consumed
        if (i + 2 < 5) stage(i + 2);
    }

#pragma unroll
    for (int w = 0; w < 3; w++) {
        __half* C = out + (size_t)w * NELEM + (size_t)slab * SLAB;
#pragma unroll
        for (int mt = 0; mt < 2; mt++) {
#pragma unroll
            for (int nt = 0; nt < 4; nt++) {
                const int r0 = m0 + wm + mt * 16 + (lane >> 2);
                const int col = n0 + wn + nt * 8 + (lane & 3) * 2;
                const size_t o0 = (size_t)r0 * SPATIAL + col;
                *(__half2*)(C + o0) =
                    __floats2half2_rn(c[w][mt][nt][0], c[w][mt][nt][1]);
                *(__half2*)(C + o0 + 8ull * SPATIAL) =
                    __floats2half2_rn(c[w][mt][nt][2], c[w][mt][nt][3]);
            }
        }
    }
}

// ================= O projection (BK=32, 3-stage, BN=256 — r15 winner) =========
#define APITCH 40
#define STG_O (64 * APITCH * 2 + 32 * (256 + 8) * 2)   // 22016

__global__ __launch_bounds__(256, 2) void o_tc(
    const __half* __restrict__ Wh, const __half* __restrict__ O,
    const float* __restrict__ bo, const __half* __restrict__ Rh,
    float* __restrict__ out)
{
    constexpr int BN = 256, BP = BN + 8;
    extern __shared__ char smem[];
    const int slab = blockIdx.z;
    const int m0 = blockIdx.y * 64;
    const int n0 = blockIdx.x * BN;
    const __half* X = O + (size_t)slab * SLAB;
    const __half* R = Rh + (size_t)slab * SLAB;
    float* C = out + (size_t)slab * SLAB;
    const __half* W = Wh + 3ull * CC * CC;

    const int tid = threadIdx.x;
    const int lane = tid & 31, wid = tid >> 5;
    const int wm = (wid & 1) * 32, wn = (wid >> 1) * (BN / 4);
    const uint32_t sb = smem_u32(smem);
    constexpr int ASZ = 64 * APITCH * 2;
    constexpr int STG = ASZ + 32 * BP * 2;

    float c[2][8][4];
#pragma unroll
    for (int a = 0; a < 2; a++)
#pragma unroll
        for (int b = 0; b < 8; b++)
#pragma unroll
            for (int d = 0; d < 4; d++) c[a][b][d] = 0.f;

    auto stage = [&](int i) {
        const int kt = i * 32;
        const uint32_t as = sb + (uint32_t)(i % 3) * STG;
        const uint32_t bs = as + (uint32_t)ASZ;
        {
            const int row = tid >> 2, ch = tid & 3;
            const __half* src = W + (size_t)(m0 + row) * CC + kt + ch * 8;
            CP_ASYNC(as + (uint32_t)(row * (APITCH * 2) + ch * 16), src, 16);
        }
#pragma unroll
        for (int t = 0; t < 4; t++) {
            const int idx = t * 256 + tid;
            const int k = idx >> 5, nc = idx & 31;
            const __half* src = X + (size_t)(kt + k) * SPATIAL + n0 + nc * 8;
            CP_ASYNC(bs + (uint32_t)(k * (BP * 2) + nc * 16), src, 16);
        }
        CP_COMMIT();
    };

    stage(0);
    stage(1);

    for (int i = 0; i < 10; i++) {
        if (i < 8) asm volatile("cp.async.wait_group 1;" ::: "memory");
        else       asm volatile("cp.async.wait_group 0;" ::: "memory");
        __syncthreads();           // single barrier per iter
        if (i + 2 < 10) stage(i + 2);

        const uint32_t as = sb + (uint32_t)(i % 3) * STG;
        const uint32_t bs = as + (uint32_t)ASZ;

#pragma unroll
        for (int ks = 0; ks < 2; ks++) {
            uint32_t af[2][4], bf[4][4];
#pragma unroll
            for (int mt = 0; mt < 2; mt++) {
                const uint32_t addr = as +
                    (uint32_t)((wm + mt * 16 + (lane & 15)) * (APITCH * 2) +
                               (lane >> 4) * 16 + ks * 32);
                ldsm4(af[mt], addr);
            }
#pragma unroll
            for (int nb = 0; nb < 4; nb++) {
                const uint32_t addr = bs +
                    (uint32_t)((ks * 16 + (lane & 15)) * (BP * 2) +
                               (wn + nb * 16 + (lane >> 4) * 8) * 2);
                ldsm4t(bf[nb], addr);
            }
#pragma unroll
            for (int nt = 0; nt < 8; nt++) {
                const uint32_t b0 = bf[nt >> 1][(nt & 1) * 2];
                const uint32_t b1 = bf[nt >> 1][(nt & 1) * 2 + 1];
                mma16(c[0][nt], af[0], b0, b1);
                mma16(c[1][nt], af[1], b0, b1);
            }
        }
    }

#pragma unroll
    for (int mt = 0; mt < 2; mt++) {
#pragma unroll
        for (int nt = 0; nt < 8; nt++) {
            const int r0 = m0 + wm + mt * 16 + (lane >> 2);
            const int col = n0 + wn + nt * 8 + (lane & 3) * 2;
            const size_t o0 = (size_t)r0 * SPATIAL + col;
            const size_t o1 = o0 + 8ull * SPATIAL;
            const float b0v = bo[r0], b1v = bo[r0 + 8];
            const float2 x0 = __half22float2(*(const __half2*)(R + o0));
            const float2 x1 = __half22float2(*(const __half2*)(R + o1));
            *(float2*)(C + o0) = make_float2(c[mt][nt][0] + b0v + x0.x,
                                             c[mt][nt][1] + b0v + x0.y);
            *(float2*)(C + o1) = make_float2(c[mt][nt][2] + b1v + x1.x,
                                             c[mt][nt][3] + b1v + x1.y);
        }
    }
}

// ================= Attention (r12/r13/r15, known good) =================
#define J4 (DH / 8)   // 5 octet-groups

__global__ __launch_bounds__(256, 2) void attn_kernel(
    const __half* __restrict__ Qg, const __half* __restrict__ Kg,
    const __half* __restrict__ Vg, __half* __restrict__ Og,
    const float* __restrict__ relk, const float* __restrict__ relv)
{
    extern __shared__ char smc[];
    uint4* Kp = (uint4*)smc;
    uint4* Vp = Kp + TT * J4 * 32;
    uint4* Rkp = Vp + TT * J4 * 32;
    uint4* Rvp = Rkp + 33 * J4;

    const int b = blockIdx.z;
    const int h = blockIdx.y;
    const int s0 = blockIdx.x * 32;
    const int tid = threadIdx.x;

    __half* Ksh = (__half*)Kp;
    __half* Vsh = (__half*)Vp;
    for (int i = tid; i < TT * DH * 4; i += 256) {
        const int row = i >> 2;
        const int ch = (i & 3) * 8;
        const int f = row / DH, dd = row - f * DH;
        const size_t g =
            ((size_t)((b * TT + f) * CC + h * DH + dd)) * SPATIAL + s0 + ch;
        uint4 kk = *(const uint4*)(Kg + g);
        uint4 vv = *(const uint4*)(Vg + g);
        __half kh[8], vh[8];
        *(uint4*)kh = kk;
        *(uint4*)vh = vv;
        const int wb = (f * J4 + (dd >> 3)) * 32;
        const int e0 = dd & 7;
#pragma unroll
        for (int e = 0; e < 8; e++) {
            const int w = (wb + ch + e) * 8 + e0;
            Ksh[w] = kh[e];
            Vsh[w] = vh[e];
        }
    }
    __half* Rkh = (__half*)Rkp;
    __half* Rvh = (__half*)Rvp;
    for (int i = tid; i < 33 * DH; i += 256) {
        Rkh[i] = __float2half_rn(relk[i]);
        Rvh[i] = __float2half_rn(relv[i]);
    }
    __syncthreads();

    const int sl = tid & 31;
    const int tg = tid >> 5;
    const float scale = 0.15811388300841898f;  // 40^-0.5

    for (int rep = 0; rep < 2; rep++) {
        const int t = rep ? (15 - tg) : tg;    // warp-uniform
        const size_t base =
            ((size_t)((b * TT + t) * CC + h * DH)) * SPATIAL + s0 + sl;

        float qo[DH];
#pragma unroll
        for (int dd = 0; dd < DH; dd++)
            qo[dd] = __half2float(Qg[base + (size_t)dd * SPATIAL]) * scale;

        float sim[TT];
        float mx = -1e30f;
#pragma unroll
        for (int sp = 0; sp < TT; sp++) {
            if (sp > t) break;
            const uint4* kp = Kp + (sp * J4) * 32 + sl;
            const uint4* rp = Rkp + (sp - t + TT) * J4;
            float p0 = 0.f, p1 = 0.f, p2 = 0.f, p3 = 0.f;
#pragma unroll
            for (int j = 0; j < J4; j++) {
                const uint4 kv = kp[j * 32];
                const uint4 rv = rp[j];
                const float2 f0 = __half22float2(__hadd2(u2h2(kv.x), u2h2(rv.x)));
                const float2 f1 = __half22float2(__hadd2(u2h2(kv.y), u2h2(rv.y)));
                const float2 f2 = __half22float2(__hadd2(u2h2(kv.z), u2h2(rv.z)));
                const float2 f3 = __half22float2(__hadd2(u2h2(kv.w), u2h2(rv.w)));
                p0 = fmaf(qo[8 * j],     f0.x, p0);
                p1 = fmaf(qo[8 * j + 1], f0.y, p1);
                p2 = fmaf(qo[8 * j + 2], f1.x, p2);
                p3 = fmaf(qo[8 * j + 3], f1.y, p3);
                p0 = fmaf(qo[8 * j + 4], f2.x, p0);
                p1 = fmaf(qo[8 * j + 5], f2.y, p1);
                p2 = fmaf(qo[8 * j + 6], f3.x, p2);
                p3 = fmaf(qo[8 * j + 7], f3.y, p3);
            }
            const float acc = (p0 + p1) + (p2 + p3);
            sim[sp] = acc;
            mx = fmaxf(mx, acc);
        }
        float den = 0.f;
#pragma unroll
        for (int sp = 0; sp < TT; sp++) {
            if (sp > t) break;
            const float e = __expf(sim[sp] - mx);
            sim[sp] = e;
            den += e;
        }
        const float inv = 1.f / den;

#pragma unroll
        for (int dd = 0; dd < DH; dd++) qo[dd] = 0.f;
#pragma unroll
        for (int sp = 0; sp < TT; sp++) {
            if (sp > t) break;
            const float a = sim[sp] * inv;
            const uint4* vp = Vp + (sp * J4) * 32 + sl;
            const uint4* rp = Rvp + (sp - t + TT) * J4;
#pragma unroll
            for (int j = 0; j < J4; j++) {
                const uint4 vv = vp[j * 32];
                const uint4 rv = rp[j];
                const float2 f0 = __half22float2(__hadd2(u2h2(vv.x), u2h2(rv.x)));
                const float2 f1 = __half22float2(__hadd2(u2h2(vv.y), u2h2(rv.y)));
                const float2 f2 = __half22float2(__hadd2(u2h2(vv.z), u2h2(rv.z)));
                const float2 f3 = __half22float2(__hadd2(u2h2(vv.w), u2h2(rv.w)));
                qo[8 * j]     = fmaf(a, f0.x, qo[8 * j]);
                qo[8 * j + 1] = fmaf(a, f0.y, qo[8 * j + 1]);
                qo[8 * j + 2] = fmaf(a, f1.x, qo[8 * j + 2]);
                qo[8 * j + 3] = fmaf(a, f1.y, qo[8 * j + 3]);
                qo[8 * j + 4] = fmaf(a, f2.x, qo[8 * j + 4]);
                qo[8 * j + 5] = fmaf(a, f2.y, qo[8 * j + 5]);
                qo[8 * j + 6] = fmaf(a, f3.x, qo[8 * j + 6]);
                qo[8 * j + 7] = fmaf(a, f3.y, qo[8 * j + 7]);
            }
        }
#pragma unroll
        for (int dd = 0; dd < DH; dd++)
            Og[base + (size_t)dd * SPATIAL] = __float2half_rn(qo[dd]);
    }
}

// ================= launch =================
extern "C" void kernel_launch(void* const* d_in, const int* in_sizes, int n_in,
                              void* d_out, int out_size) {
    const float* x  = (const float*)d_in[0];
    const float* Wq = (const float*)d_in[1];
    const float* Wk = (const float*)d_in[2];
    const float* Wv = (const float*)d_in[3];
    const float* Wo = (const float*)d_in[4];
    const float* bo = (const float*)d_in[5];
    const float* rk = (const float*)d_in[6];
    const float* rv = (const float*)d_in[7];
    float* out = (float*)d_out;

    __half* hb = nullptr;
    cudaGetSymbolAddress((void**)&hb, g_hbuf);
    __half* Q  = hb;
    __half* K  = hb + 1ull * NELEM;
    __half* V  = hb + 2ull * NELEM;
    __half* O  = hb + 3ull * NELEM;
    __half* Xh = hb + 4ull * NELEM;
    __half* Wh = hb + 5ull * NELEM;

    cvt_all<<<XB + WB, 256>>>(x, Wq, Wk, Wv, Wo, Xh, Wh);

    cudaFuncSetAttribute((const void*)qkv_tc,
                         cudaFuncAttributeMaxDynamicSharedMemorySize, 2 * QSTG2);
    cudaFuncSetAttribute((const void*)o_tc,
                         cudaFuncAttributeMaxDynamicSharedMemorySize, 3 * STG_O);

    qkv_tc<<<dim3(SPATIAL / 128, CC / 64, NSLAB), 256, 2 * QSTG2>>>(Wh, Xh, hb);

    const int asmb = 87200;
    cudaFuncSetAttribute((const void*)attn_kernel,
                         cudaFuncAttributeMaxDynamicSharedMemorySize, asmb);
    attn_kernel<<<dim3(SPATIAL / 32, HEADS, 4), 256, asmb>>>(Q, K, V, O, rk, rv);

    o_tc<<<dim3(SPATIAL / 256, CC / 64, NSLAB), 256, 3 * STG_O>>>(Wh, O, bo, Xh, out);
}